// round 1
// baseline (speedup 1.0000x reference)
#include <cuda_runtime.h>
#include <math.h>

#define NN 50000
#define NE 800000
#define D  128

// ---------------- scratch (static device allocations; no runtime alloc) ----------------
static __device__ float g_Q  [NN * D];
static __device__ float g_Kb [NN * D];
static __device__ float g_V  [NN * D];
static __device__ float g_pe [NE * D];      // pe, overwritten in place with e_attn_out
static __device__ float g_wV [NN * D];
static __device__ float g_z  [NN * 8];
static __device__ float g_h2 [NN * D];      // h2 pre-BN
static __device__ float g_e2 [NE * D];      // e2 pre-BN
static __device__ float g_mid[NE * 256];    // FFN hidden (reused for h and e)
static __device__ float g_stats[4 * 2 * D]; // per-bn: sum[128], sumsq[128]
static __device__ float g_bnab [4 * 2 * D]; // per-bn: scale[128], shift[128]

// ---------------- generic 128/256-wide GEMM with fused epilogues ----------------
// C[M,NOUT] = op( X'[M,K] @ W[K,NOUT] + bias + residual )
//   BN_IN : X' = X*in_ab[k] + in_ab[K+k]   (fold BN of previous stage into load)
//   RESM  : 0 none, 1 plain residual, 2 residual transformed by res_ab (BN'd residual)
//   DO_STATS: accumulate column sum/sumsq of the stored value into stats[2*NOUT]
template<int K, int NOUT, int BN_IN, int DO_RELU, int HAS_BIAS, int RESM, int DO_STATS>
__global__ void __launch_bounds__(256)
gemm_k(const float* __restrict__ X, const float* __restrict__ W,
       const float* __restrict__ bias, const float* __restrict__ res,
       const float* __restrict__ in_ab, const float* __restrict__ res_ab,
       float* __restrict__ C, float* __restrict__ stats, int M)
{
    constexpr int BM = 64, KC = 16, CW = NOUT / 16;
    extern __shared__ float sm[];
    float* Xs = sm;                 // BM*K
    float* Ws = sm + BM * K;        // KC*NOUT  (reused as stats scratch at the end)
    const int tid  = threadIdx.x;
    const int trow = tid >> 4, tcol = tid & 15;
    const int row0 = blockIdx.x * BM;

    // load X tile (vectorized), zero-pad invalid rows, optionally fold BN
    {
        const int KV = K / 4;
        for (int i = tid; i < BM * KV; i += 256) {
            int r = i / KV, c4 = i - r * KV;
            int gr = row0 + r;
            float4 v = make_float4(0.f, 0.f, 0.f, 0.f);
            if (gr < M) {
                v = __ldg(reinterpret_cast<const float4*>(X + (size_t)gr * K) + c4);
                if (BN_IN) {
                    int k = c4 * 4;
                    v.x = fmaf(v.x, __ldg(in_ab + k + 0), __ldg(in_ab + K + k + 0));
                    v.y = fmaf(v.y, __ldg(in_ab + k + 1), __ldg(in_ab + K + k + 1));
                    v.z = fmaf(v.z, __ldg(in_ab + k + 2), __ldg(in_ab + K + k + 2));
                    v.w = fmaf(v.w, __ldg(in_ab + k + 3), __ldg(in_ab + K + k + 3));
                }
            }
            *reinterpret_cast<float4*>(Xs + r * K + c4 * 4) = v;
        }
    }

    float acc[4][CW];
    #pragma unroll
    for (int r = 0; r < 4; r++)
        #pragma unroll
        for (int c = 0; c < CW; c++) acc[r][c] = 0.f;

    for (int k0 = 0; k0 < K; k0 += KC) {
        __syncthreads();
        for (int i = tid; i < KC * (NOUT / 4); i += 256) {
            int kk = i / (NOUT / 4), c4 = i - kk * (NOUT / 4);
            reinterpret_cast<float4*>(Ws)[i] =
                __ldg(reinterpret_cast<const float4*>(W + (size_t)(k0 + kk) * NOUT) + c4);
        }
        __syncthreads();
        #pragma unroll
        for (int kk = 0; kk < KC; kk++) {
            float a[4];
            #pragma unroll
            for (int r = 0; r < 4; r++) a[r] = Xs[(trow * 4 + r) * K + k0 + kk];
            float b[CW];
            #pragma unroll
            for (int c4 = 0; c4 < CW / 4; c4++) {
                float4 bv = *reinterpret_cast<const float4*>(Ws + kk * NOUT + tcol * CW + c4 * 4);
                b[c4 * 4 + 0] = bv.x; b[c4 * 4 + 1] = bv.y;
                b[c4 * 4 + 2] = bv.z; b[c4 * 4 + 3] = bv.w;
            }
            #pragma unroll
            for (int r = 0; r < 4; r++)
                #pragma unroll
                for (int c = 0; c < CW; c++)
                    acc[r][c] = fmaf(a[r], b[c], acc[r][c]);
        }
    }

    // epilogue
    float bb[CW], rsc[CW], rsh[CW];
    #pragma unroll
    for (int c = 0; c < CW; c++) {
        int col = tcol * CW + c;
        bb[c] = HAS_BIAS ? __ldg(bias + col) : 0.f;
        if (RESM == 2) { rsc[c] = __ldg(res_ab + col); rsh[c] = __ldg(res_ab + NOUT + col); }
        else           { rsc[c] = 0.f; rsh[c] = 0.f; }
    }
    float s1[CW], s2[CW];
    #pragma unroll
    for (int c = 0; c < CW; c++) { s1[c] = 0.f; s2[c] = 0.f; }

    #pragma unroll
    for (int r = 0; r < 4; r++) {
        int gr = row0 + trow * 4 + r;
        if (gr >= M) continue;
        float rv[CW];
        if (RESM != 0) {
            #pragma unroll
            for (int c4 = 0; c4 < CW / 4; c4++) {
                float4 t = __ldg(reinterpret_cast<const float4*>(res + (size_t)gr * NOUT + tcol * CW) + c4);
                rv[c4 * 4 + 0] = t.x; rv[c4 * 4 + 1] = t.y;
                rv[c4 * 4 + 2] = t.z; rv[c4 * 4 + 3] = t.w;
            }
        }
        float outv[CW];
        #pragma unroll
        for (int c = 0; c < CW; c++) {
            float v = acc[r][c] + bb[c];
            if (RESM == 1) v += rv[c];
            if (RESM == 2) v = fmaf(rv[c], rsc[c], v + rsh[c]);
            if (DO_RELU)   v = fmaxf(v, 0.f);
            outv[c] = v;
            if (DO_STATS) { s1[c] += v; s2[c] = fmaf(v, v, s2[c]); }
        }
        #pragma unroll
        for (int c4 = 0; c4 < CW / 4; c4++)
            *reinterpret_cast<float4*>(C + (size_t)gr * NOUT + tcol * CW + c4 * 4) =
                make_float4(outv[c4 * 4], outv[c4 * 4 + 1], outv[c4 * 4 + 2], outv[c4 * 4 + 3]);
    }

    if (DO_STATS) {
        float* ss = Ws;   // KC*NOUT >= 2*NOUT floats
        __syncthreads();
        for (int i = tid; i < 2 * NOUT; i += 256) ss[i] = 0.f;
        __syncthreads();
        #pragma unroll
        for (int c = 0; c < CW; c++) {
            atomicAdd(&ss[tcol * CW + c], s1[c]);
            atomicAdd(&ss[NOUT + tcol * CW + c], s2[c]);
        }
        __syncthreads();
        for (int i = tid; i < 2 * NOUT; i += 256) atomicAdd(&stats[i], ss[i]);
    }
}

// ---------------- edge attention: score, e_attn_out (in place over pe), exp, scatter ----------------
__global__ void edge_kernel(const int* __restrict__ src, const int* __restrict__ dst)
{
    int w    = (blockIdx.x * blockDim.x + threadIdx.x) >> 5;   // one warp per edge
    int lane = threadIdx.x & 31;
    if (w >= NE) return;
    int s = __ldg(src + w), d = __ldg(dst + w);

    float4 q = __ldg(reinterpret_cast<const float4*>(g_Q  + (size_t)d * D) + lane);
    float4 k = __ldg(reinterpret_cast<const float4*>(g_Kb + (size_t)s * D) + lane);
    float4 p = *(reinterpret_cast<const float4*>(g_pe + (size_t)w * D) + lane);

    float4 sc;                                   // K[src]*Q[dst]/sqrt(16) * pe
    sc.x = k.x * q.x * 0.25f * p.x;
    sc.y = k.y * q.y * 0.25f * p.y;
    sc.z = k.z * q.z * 0.25f * p.z;
    sc.w = k.w * q.w * 0.25f * p.w;
    *(reinterpret_cast<float4*>(g_pe + (size_t)w * D) + lane) = sc;   // e_attn_out

    float part = sc.x + sc.y + sc.z + sc.w;      // head = lane/4 (16 floats per head)
    part += __shfl_xor_sync(0xffffffffu, part, 1);
    part += __shfl_xor_sync(0xffffffffu, part, 2);
    part  = fminf(fmaxf(part, -5.f), 5.f);
    float sh = expf(part);

    float4 v = __ldg(reinterpret_cast<const float4*>(g_V + (size_t)s * D) + lane);
    float* wv = g_wV + (size_t)d * D + lane * 4;
    atomicAdd(wv + 0, v.x * sh);
    atomicAdd(wv + 1, v.y * sh);
    atomicAdd(wv + 2, v.z * sh);
    atomicAdd(wv + 3, v.w * sh);
    if ((lane & 3) == 0) atomicAdd(g_z + (size_t)d * 8 + (lane >> 2), sh);
}

// h_attn = wV / (z + 1e-6), in place
__global__ void hattn_div()
{
    int i = blockIdx.x * blockDim.x + threadIdx.x;
    if (i < NN * D) {
        int node = i >> 7, c = i & 127;
        g_wV[i] = g_wV[i] / (g_z[node * 8 + (c >> 4)] + 1e-6f);
    }
}

// stats -> (scale, shift) for batchnorm:  y = x*scale + shift
__global__ void finalize_bn(int bn, const float* __restrict__ g, const float* __restrict__ b, float minv)
{
    int c = threadIdx.x;
    float mean = g_stats[bn * 2 * D + c] * minv;
    float var  = g_stats[bn * 2 * D + D + c] * minv - mean * mean;
    float rstd = rsqrtf(var + 1e-5f);
    float scv  = g[c] * rstd;
    g_bnab[bn * 2 * D + c]     = scv;
    g_bnab[bn * 2 * D + D + c] = b[c] - mean * scv;
}

// in-place BN of the output buffer: h region uses bn2, e region uses bn3
__global__ void out_norm(float* __restrict__ out)
{
    int i = blockIdx.x * blockDim.x + threadIdx.x;
    if (i < (NN + NE) * D) {
        int c  = i & 127;
        int bn = (i < NN * D) ? 2 : 3;
        out[i] = fmaf(out[i], g_bnab[bn * 2 * D + c], g_bnab[bn * 2 * D + D + c]);
    }
}

// ---------------- host launch ----------------
extern "C" void kernel_launch(void* const* d_in, const int* in_sizes, int n_in,
                              void* d_out, int out_size)
{
    (void)in_sizes; (void)n_in; (void)out_size;
    const float* h_in  = (const float*)d_in[0];
    const float* e_in  = (const float*)d_in[1];
    const float* Wq    = (const float*)d_in[2];
    const float* Wk    = (const float*)d_in[3];
    const float* Wv    = (const float*)d_in[4];
    const float* We    = (const float*)d_in[5];
    const float* Ohw   = (const float*)d_in[6];
    const float* Ohb   = (const float*)d_in[7];
    const float* Oew   = (const float*)d_in[8];
    const float* Oeb   = (const float*)d_in[9];
    const float* bn1hg = (const float*)d_in[10];
    const float* bn1hb = (const float*)d_in[11];
    const float* bn1eg = (const float*)d_in[12];
    const float* bn1eb = (const float*)d_in[13];
    const float* fhw1  = (const float*)d_in[14];
    const float* fhb1  = (const float*)d_in[15];
    const float* fhw2  = (const float*)d_in[16];
    const float* fhb2  = (const float*)d_in[17];
    const float* few1  = (const float*)d_in[18];
    const float* feb1  = (const float*)d_in[19];
    const float* few2  = (const float*)d_in[20];
    const float* feb2  = (const float*)d_in[21];
    const float* bn2hg = (const float*)d_in[22];
    const float* bn2hb = (const float*)d_in[23];
    const float* bn2eg = (const float*)d_in[24];
    const float* bn2eb = (const float*)d_in[25];
    const int*   src   = (const int*)d_in[26];
    const int*   dst   = (const int*)d_in[27];

    float* out  = (float*)d_out;
    float* outh = out;
    float* oute = out + (size_t)NN * D;

    float *pQ, *pK, *pV, *ppe, *pwV, *pz, *ph2, *pe2, *pmid, *pstats, *pbnab;
    cudaGetSymbolAddress((void**)&pQ,    g_Q);
    cudaGetSymbolAddress((void**)&pK,    g_Kb);
    cudaGetSymbolAddress((void**)&pV,    g_V);
    cudaGetSymbolAddress((void**)&ppe,   g_pe);
    cudaGetSymbolAddress((void**)&pwV,   g_wV);
    cudaGetSymbolAddress((void**)&pz,    g_z);
    cudaGetSymbolAddress((void**)&ph2,   g_h2);
    cudaGetSymbolAddress((void**)&pe2,   g_e2);
    cudaGetSymbolAddress((void**)&pmid,  g_mid);
    cudaGetSymbolAddress((void**)&pstats, g_stats);
    cudaGetSymbolAddress((void**)&pbnab,  g_bnab);

    // kernel variants
    auto kA = gemm_k<128, 128, 0, 0, 0, 0, 0>;  // plain C = X@W
    auto kB = gemm_k<128, 128, 0, 0, 1, 1, 1>;  // + bias + residual + stats
    auto kC = gemm_k<128, 256, 1, 1, 1, 0, 0>;  // BN(input) -> relu(X@W1+b1)
    auto kD = gemm_k<256, 128, 0, 0, 1, 2, 1>;  // X@W2+b2 + BN(residual) + stats

    const int SM_AB = (64 * 128 + 16 * 128) * 4;   // 40 KB
    const int SM_C  = (64 * 128 + 16 * 256) * 4;   // 48 KB
    const int SM_D  = (64 * 256 + 16 * 128) * 4;   // 72 KB
    cudaFuncSetAttribute(kA, cudaFuncAttributeMaxDynamicSharedMemorySize, SM_AB);
    cudaFuncSetAttribute(kB, cudaFuncAttributeMaxDynamicSharedMemorySize, SM_AB);
    cudaFuncSetAttribute(kC, cudaFuncAttributeMaxDynamicSharedMemorySize, SM_C);
    cudaFuncSetAttribute(kD, cudaFuncAttributeMaxDynamicSharedMemorySize, SM_D);

    cudaMemsetAsync(pwV,    0, sizeof(float) * NN * D);
    cudaMemsetAsync(pz,     0, sizeof(float) * NN * 8);
    cudaMemsetAsync(pstats, 0, sizeof(float) * 4 * 2 * D);

    const int gN = (NN + 63) / 64;     // 782
    const int gE = (NE + 63) / 64;     // 12500

    // Q, K, V, pe projections
    kA<<<gN, 256, SM_AB>>>(h_in, Wq, nullptr, nullptr, nullptr, nullptr, pQ,  nullptr, NN);
    kA<<<gN, 256, SM_AB>>>(h_in, Wk, nullptr, nullptr, nullptr, nullptr, pK,  nullptr, NN);
    kA<<<gN, 256, SM_AB>>>(h_in, Wv, nullptr, nullptr, nullptr, nullptr, pV,  nullptr, NN);
    kA<<<gE, 256, SM_AB>>>(e_in, We, nullptr, nullptr, nullptr, nullptr, ppe, nullptr, NE);

    // edge attention + scatter
    edge_kernel<<<(NE + 7) / 8, 256>>>(src, dst);
    hattn_div<<<(NN * D + 255) / 256, 256>>>();

    // O projections + residual, accumulate bn1 stats
    kB<<<gN, 256, SM_AB>>>(pwV, Ohw, Ohb, h_in, nullptr, nullptr, ph2, pstats + 0 * 2 * D, NN);
    kB<<<gE, 256, SM_AB>>>(ppe, Oew, Oeb, e_in, nullptr, nullptr, pe2, pstats + 1 * 2 * D, NE);
    finalize_bn<<<1, D>>>(0, bn1hg, bn1hb, 1.f / NN);
    finalize_bn<<<1, D>>>(1, bn1eg, bn1eb, 1.f / NE);

    // h FFN: mid = relu(bn1h(h2pre)@W1+b1); out_h = mid@W2+b2 + bn1h(h2pre); bn2h stats
    kC<<<gN, 256, SM_C>>>(ph2,  fhw1, fhb1, nullptr, pbnab + 0 * 2 * D, nullptr, pmid, nullptr, NN);
    kD<<<gN, 256, SM_D>>>(pmid, fhw2, fhb2, ph2, nullptr, pbnab + 0 * 2 * D, outh, pstats + 2 * 2 * D, NN);

    // e FFN
    kC<<<gE, 256, SM_C>>>(pe2,  few1, feb1, nullptr, pbnab + 1 * 2 * D, nullptr, pmid, nullptr, NE);
    kD<<<gE, 256, SM_D>>>(pmid, few2, feb2, pe2, nullptr, pbnab + 1 * 2 * D, oute, pstats + 3 * 2 * D, NE);

    finalize_bn<<<1, D>>>(2, bn2hg, bn2hb, 1.f / NN);
    finalize_bn<<<1, D>>>(3, bn2eg, bn2eb, 1.f / NE);

    // final in-place BN of the output buffer
    out_norm<<<((NN + NE) * D + 255) / 256, 256>>>(out);
}

// round 3
// speedup vs baseline: 2.6216x; 2.6216x over previous
#include <cuda_runtime.h>
#include <cuda_bf16.h>
#include <math.h>
#include <stdint.h>

#define NN 50000
#define NE 800000
#define D  128

// ---------------- scratch ----------------
static __device__ float g_Q  [NN * D];
static __device__ float g_Kb [NN * D];
static __device__ float g_V  [NN * D];
static __device__ float g_wV [NN * D];
static __device__ float g_z  [NN * 8];
static __device__ float g_h2 [NN * D];
static __device__ float g_pe [(size_t)NE * D];
static __device__ float g_e2 [(size_t)NE * D];
static __device__ float g_mid[(size_t)NE * 256];
static __device__ float g_stats[4 * 2 * D];
static __device__ float g_bnab [4 * 2 * D];
static __device__ __nv_bfloat16 g_wimg[458752];   // fragment-ordered bf16 hi/lo weight images

// ---------------- weight prep ----------------
// W[K,N] fp32 -> b-fragment-ordered bf16 image.
// For mma.sync m16n8k16 row.col, lane l of a warp holds B^T[n = ntile*8 + (l>>2)][k = kstep*16 + (l&3)*2 + {0,1} (+8 for reg1)].
// Image layout (uint32 granularity = bf16x2):
//   u32_index = ((kstep * (N/8) + ntile) * 32 + lane) * 2 + reg
// hi image at img[0], lo image at img[K*N] (bf16 elements).
__global__ void prep_w(const float* __restrict__ W, int K, int N, __nv_bfloat16* __restrict__ img)
{
    int idx = blockIdx.x * blockDim.x + threadIdx.x;
    if (idx >= K * N) return;
    int k = idx / N, n = idx - k * N;
    float w = __ldg(W + idx);
    __nv_bfloat16 hi = __float2bfloat16(w);
    __nv_bfloat16 lo = __float2bfloat16(w - __bfloat162float(hi));
    int kstep = k >> 4, kin = k & 15;
    int reg  = (kin >> 3) & 1;
    int tid4 = (kin >> 1) & 3;
    int p    = kin & 1;
    int g    = n & 7;
    int ntile = n >> 3;
    int lane = g * 4 + tid4;
    size_t off = ((((size_t)kstep * (N >> 3) + ntile) * 32 + lane) * 2 + reg) * 2 + p;
    img[off] = hi;
    img[off + (size_t)K * N] = lo;
}

// ---------------- mma.sync bf16-split GEMM ----------------
__device__ __forceinline__ void mma16816(float* c, const uint32_t* a, uint32_t b0, uint32_t b1)
{
    asm volatile(
        "mma.sync.aligned.m16n8k16.row.col.f32.bf16.bf16.f32 "
        "{%0,%1,%2,%3}, {%4,%5,%6,%7}, {%8,%9}, {%0,%1,%2,%3};"
        : "+f"(c[0]), "+f"(c[1]), "+f"(c[2]), "+f"(c[3])
        : "r"(a[0]), "r"(a[1]), "r"(a[2]), "r"(a[3]), "r"(b0), "r"(b1));
}

// C[M,NT] = epi( X[M,KT] @ W )  with block tile 128x128, grid = (ceil(M/128), NT/128)
//   BN_IN: fold y = x*in_ab[k] + in_ab[KT+k] into the A load
//   RESM : 0 none, 1 plain residual, 2 residual scaled by res_ab (BN'd residual)
template<int KT, int NT, int BN_IN, int RELU, int BIAS, int RESM>
__global__ void __launch_bounds__(256)
mm_k(const float* __restrict__ X, const __nv_bfloat16* __restrict__ Wimg,
     const float* __restrict__ bias, const float* __restrict__ res,
     const float* __restrict__ in_ab, const float* __restrict__ res_ab,
     float* __restrict__ C, int M)
{
    constexpr int SAP = 136;                 // smem A row stride (bf16) -> conflict-free frags
    extern __shared__ __nv_bfloat16 sA[];    // [hi: 128*SAP][lo: 128*SAP]
    __nv_bfloat16* Ah = sA;
    __nv_bfloat16* Al = sA + 128 * SAP;

    const int tid  = threadIdx.x;
    const int w    = tid >> 5, lane = tid & 31;
    const int wr   = w >> 1, wc = w & 1;       // 4x2 warp grid; warp tile 32x64
    const int g    = lane >> 2, tid4 = lane & 3;
    const int row0 = blockIdx.x * 128;
    const int ntile0 = blockIdx.y * 16;        // 16 ntiles per 128-col block

    const uint2* Bh = (const uint2*)Wimg;
    const uint2* Bl = (const uint2*)(Wimg + (size_t)KT * NT);

    float acc[2][8][4];
    #pragma unroll
    for (int mt = 0; mt < 2; mt++)
        #pragma unroll
        for (int nt = 0; nt < 8; nt++)
            #pragma unroll
            for (int i = 0; i < 4; i++) acc[mt][nt][i] = 0.f;

    for (int kc = 0; kc < KT / 128; kc++) {
        // ---- stage A chunk [128 rows x 128 k] as bf16 hi/lo ----
        #pragma unroll 4
        for (int i = tid; i < 4096; i += 256) {
            int r = i >> 5, c4 = i & 31, col = c4 * 4;
            float4 v = make_float4(0.f, 0.f, 0.f, 0.f);
            int gr = row0 + r;
            if (gr < M) {
                v = __ldg((const float4*)(X + (size_t)gr * KT + kc * 128) + c4);
                if (BN_IN) {
                    int kk = kc * 128 + col;
                    v.x = fmaf(v.x, __ldg(in_ab + kk + 0), __ldg(in_ab + KT + kk + 0));
                    v.y = fmaf(v.y, __ldg(in_ab + kk + 1), __ldg(in_ab + KT + kk + 1));
                    v.z = fmaf(v.z, __ldg(in_ab + kk + 2), __ldg(in_ab + KT + kk + 2));
                    v.w = fmaf(v.w, __ldg(in_ab + kk + 3), __ldg(in_ab + KT + kk + 3));
                }
            }
            __nv_bfloat162 h0 = __floats2bfloat162_rn(v.x, v.y);
            __nv_bfloat162 h1 = __floats2bfloat162_rn(v.z, v.w);
            __nv_bfloat162 l0 = __floats2bfloat162_rn(v.x - __bfloat162float(h0.x),
                                                      v.y - __bfloat162float(h0.y));
            __nv_bfloat162 l1 = __floats2bfloat162_rn(v.z - __bfloat162float(h1.x),
                                                      v.w - __bfloat162float(h1.y));
            *(__nv_bfloat162*)(Ah + r * SAP + col)     = h0;
            *(__nv_bfloat162*)(Ah + r * SAP + col + 2) = h1;
            *(__nv_bfloat162*)(Al + r * SAP + col)     = l0;
            *(__nv_bfloat162*)(Al + r * SAP + col + 2) = l1;
        }
        __syncthreads();

        // ---- compute ----
        #pragma unroll
        for (int ks = 0; ks < 8; ks++) {
            const int gks = kc * 8 + ks;
            uint32_t ah[2][4], al[2][4];
            #pragma unroll
            for (int mt = 0; mt < 2; mt++) {
                int r0 = wr * 32 + mt * 16 + g;
                int kk = ks * 16 + tid4 * 2;
                ah[mt][0] = *(const uint32_t*)(Ah + (r0    ) * SAP + kk);
                ah[mt][1] = *(const uint32_t*)(Ah + (r0 + 8) * SAP + kk);
                ah[mt][2] = *(const uint32_t*)(Ah + (r0    ) * SAP + kk + 8);
                ah[mt][3] = *(const uint32_t*)(Ah + (r0 + 8) * SAP + kk + 8);
                al[mt][0] = *(const uint32_t*)(Al + (r0    ) * SAP + kk);
                al[mt][1] = *(const uint32_t*)(Al + (r0 + 8) * SAP + kk);
                al[mt][2] = *(const uint32_t*)(Al + (r0    ) * SAP + kk + 8);
                al[mt][3] = *(const uint32_t*)(Al + (r0 + 8) * SAP + kk + 8);
            }
            #pragma unroll
            for (int nt = 0; nt < 8; nt++) {
                size_t bidx = ((size_t)gks * (NT / 8) + (ntile0 + wc * 8 + nt)) * 32 + lane;
                uint2 bh = __ldg(Bh + bidx);
                uint2 bl = __ldg(Bl + bidx);
                #pragma unroll
                for (int mt = 0; mt < 2; mt++) mma16816(acc[mt][nt], ah[mt], bh.x, bh.y);
                #pragma unroll
                for (int mt = 0; mt < 2; mt++) mma16816(acc[mt][nt], ah[mt], bl.x, bl.y);
                #pragma unroll
                for (int mt = 0; mt < 2; mt++) mma16816(acc[mt][nt], al[mt], bh.x, bh.y);
            }
        }
        __syncthreads();
    }

    // ---- epilogue ----
    #pragma unroll
    for (int mt = 0; mt < 2; mt++) {
        #pragma unroll
        for (int half = 0; half < 2; half++) {
            int gr = row0 + wr * 32 + mt * 16 + g + half * 8;
            if (gr >= M) continue;
            #pragma unroll
            for (int nt = 0; nt < 8; nt++) {
                int col = blockIdx.y * 128 + wc * 64 + nt * 8 + tid4 * 2;
                float o0 = acc[mt][nt][half * 2 + 0];
                float o1 = acc[mt][nt][half * 2 + 1];
                if (BIAS) { o0 += __ldg(bias + col); o1 += __ldg(bias + col + 1); }
                if (RESM) {
                    float2 rv = __ldg((const float2*)(res + (size_t)gr * NT + col));
                    if (RESM == 1) { o0 += rv.x; o1 += rv.y; }
                    else {
                        o0 = fmaf(rv.x, __ldg(res_ab + col),     o0 + __ldg(res_ab + NT + col));
                        o1 = fmaf(rv.y, __ldg(res_ab + col + 1), o1 + __ldg(res_ab + NT + col + 1));
                    }
                }
                if (RELU) { o0 = fmaxf(o0, 0.f); o1 = fmaxf(o1, 0.f); }
                *(float2*)(C + (size_t)gr * NT + col) = make_float2(o0, o1);
            }
        }
    }
}

// ---------------- edge attention ----------------
__global__ void edge_kernel(const int* __restrict__ src, const int* __restrict__ dst)
{
    int w    = (blockIdx.x * blockDim.x + threadIdx.x) >> 5;
    int lane = threadIdx.x & 31;
    if (w >= NE) return;
    int s = __ldg(src + w), d = __ldg(dst + w);

    float4 q = __ldg(reinterpret_cast<const float4*>(g_Q  + (size_t)d * D) + lane);
    float4 k = __ldg(reinterpret_cast<const float4*>(g_Kb + (size_t)s * D) + lane);
    float4 p = *(reinterpret_cast<const float4*>(g_pe + (size_t)w * D) + lane);

    float4 sc;
    sc.x = k.x * q.x * 0.25f * p.x;
    sc.y = k.y * q.y * 0.25f * p.y;
    sc.z = k.z * q.z * 0.25f * p.z;
    sc.w = k.w * q.w * 0.25f * p.w;
    *(reinterpret_cast<float4*>(g_pe + (size_t)w * D) + lane) = sc;

    float part = sc.x + sc.y + sc.z + sc.w;
    part += __shfl_xor_sync(0xffffffffu, part, 1);
    part += __shfl_xor_sync(0xffffffffu, part, 2);
    part  = fminf(fmaxf(part, -5.f), 5.f);
    float sh = expf(part);

    float4 v = __ldg(reinterpret_cast<const float4*>(g_V + (size_t)s * D) + lane);
    float* wv = g_wV + (size_t)d * D + lane * 4;
    atomicAdd(wv + 0, v.x * sh);
    atomicAdd(wv + 1, v.y * sh);
    atomicAdd(wv + 2, v.z * sh);
    atomicAdd(wv + 3, v.w * sh);
    if ((lane & 3) == 0) atomicAdd(g_z + (size_t)d * 8 + (lane >> 2), sh);
}

__global__ void hattn_div()
{
    int i = blockIdx.x * blockDim.x + threadIdx.x;
    if (i < NN * D) {
        int node = i >> 7, c = i & 127;
        g_wV[i] = g_wV[i] / (g_z[node * 8 + (c >> 4)] + 1e-6f);
    }
}

// ---------------- streaming column stats ----------------
__global__ void colstats(const float* __restrict__ X, int M, float* __restrict__ stats)
{
    __shared__ float ss[256];
    int tid = threadIdx.x;
    int cg = tid & 31, rl = tid >> 5;
    float s1[4] = {0, 0, 0, 0}, s2[4] = {0, 0, 0, 0};
    for (int r = blockIdx.x * 8 + rl; r < M; r += gridDim.x * 8) {
        float4 v = __ldg((const float4*)(X + (size_t)r * 128) + cg);
        s1[0] += v.x; s2[0] = fmaf(v.x, v.x, s2[0]);
        s1[1] += v.y; s2[1] = fmaf(v.y, v.y, s2[1]);
        s1[2] += v.z; s2[2] = fmaf(v.z, v.z, s2[2]);
        s1[3] += v.w; s2[3] = fmaf(v.w, v.w, s2[3]);
    }
    ss[tid] = 0.f;
    __syncthreads();
    #pragma unroll
    for (int j = 0; j < 4; j++) {
        atomicAdd(&ss[cg * 4 + j], s1[j]);
        atomicAdd(&ss[128 + cg * 4 + j], s2[j]);
    }
    __syncthreads();
    atomicAdd(&stats[tid], ss[tid]);
}

__global__ void finalize_bn(int bn, const float* __restrict__ g, const float* __restrict__ b, float minv)
{
    int c = threadIdx.x;
    float mean = g_stats[bn * 2 * D + c] * minv;
    float var  = g_stats[bn * 2 * D + D + c] * minv - mean * mean;
    float rstd = rsqrtf(var + 1e-5f);
    float scv  = g[c] * rstd;
    g_bnab[bn * 2 * D + c]     = scv;
    g_bnab[bn * 2 * D + D + c] = b[c] - mean * scv;
}

__global__ void out_norm(float* __restrict__ out)
{
    size_t i = (size_t)blockIdx.x * blockDim.x + threadIdx.x;
    if (i < (size_t)(NN + NE) * D) {
        int c  = (int)(i & 127);
        int bn = (i < (size_t)NN * D) ? 2 : 3;
        out[i] = fmaf(out[i], g_bnab[bn * 2 * D + c], g_bnab[bn * 2 * D + D + c]);
    }
}

// ---------------- host ----------------
extern "C" void kernel_launch(void* const* d_in, const int* in_sizes, int n_in,
                              void* d_out, int out_size)
{
    (void)in_sizes; (void)n_in; (void)out_size;
    const float* h_in  = (const float*)d_in[0];
    const float* e_in  = (const float*)d_in[1];
    const float* Wq    = (const float*)d_in[2];
    const float* Wk    = (const float*)d_in[3];
    const float* Wv    = (const float*)d_in[4];
    const float* We    = (const float*)d_in[5];
    const float* Ohw   = (const float*)d_in[6];
    const float* Ohb   = (const float*)d_in[7];
    const float* Oew   = (const float*)d_in[8];
    const float* Oeb   = (const float*)d_in[9];
    const float* bn1hg = (const float*)d_in[10];
    const float* bn1hb = (const float*)d_in[11];
    const float* bn1eg = (const float*)d_in[12];
    const float* bn1eb = (const float*)d_in[13];
    const float* fhw1  = (const float*)d_in[14];
    const float* fhb1  = (const float*)d_in[15];
    const float* fhw2  = (const float*)d_in[16];
    const float* fhb2  = (const float*)d_in[17];
    const float* few1  = (const float*)d_in[18];
    const float* feb1  = (const float*)d_in[19];
    const float* few2  = (const float*)d_in[20];
    const float* feb2  = (const float*)d_in[21];
    const float* bn2hg = (const float*)d_in[22];
    const float* bn2hb = (const float*)d_in[23];
    const float* bn2eg = (const float*)d_in[24];
    const float* bn2eb = (const float*)d_in[25];
    const int*   src   = (const int*)d_in[26];
    const int*   dst   = (const int*)d_in[27];

    float* out  = (float*)d_out;
    float* outh = out;
    float* oute = out + (size_t)NN * D;

    float *pQ, *pK, *pV, *ppe, *pwV, *pz, *ph2, *pe2, *pmid, *pstats, *pbnab;
    __nv_bfloat16* pimg;
    cudaGetSymbolAddress((void**)&pQ,    g_Q);
    cudaGetSymbolAddress((void**)&pK,    g_Kb);
    cudaGetSymbolAddress((void**)&pV,    g_V);
    cudaGetSymbolAddress((void**)&ppe,   g_pe);
    cudaGetSymbolAddress((void**)&pwV,   g_wV);
    cudaGetSymbolAddress((void**)&pz,    g_z);
    cudaGetSymbolAddress((void**)&ph2,   g_h2);
    cudaGetSymbolAddress((void**)&pe2,   g_e2);
    cudaGetSymbolAddress((void**)&pmid,  g_mid);
    cudaGetSymbolAddress((void**)&pstats, g_stats);
    cudaGetSymbolAddress((void**)&pbnab,  g_bnab);
    cudaGetSymbolAddress((void**)&pimg,   g_wimg);

    // weight image offsets (bf16 elements; each weight takes 2*K*N)
    const size_t oWq = 0, oWk = 32768, oWv = 65536, oWe = 98304;
    const size_t oOh = 131072, oOe = 163840;
    const size_t oF1h = 196608, oF1e = 262144, oF2h = 327680, oF2e = 393216;

    auto kA = mm_k<128, 128, 0, 0, 0, 0>;  // plain
    auto kB = mm_k<128, 128, 0, 0, 1, 1>;  // +bias +residual
    auto kC = mm_k<128, 256, 1, 1, 1, 0>;  // BN(in) -> relu(X@W1+b1)
    auto kD = mm_k<256, 128, 0, 0, 1, 2>;  // +bias +BN(residual)

    const int SMEM = 2 * 128 * 136 * 2;    // 69632 B
    cudaFuncSetAttribute(kA, cudaFuncAttributeMaxDynamicSharedMemorySize, SMEM);
    cudaFuncSetAttribute(kB, cudaFuncAttributeMaxDynamicSharedMemorySize, SMEM);
    cudaFuncSetAttribute(kC, cudaFuncAttributeMaxDynamicSharedMemorySize, SMEM);
    cudaFuncSetAttribute(kD, cudaFuncAttributeMaxDynamicSharedMemorySize, SMEM);

    cudaMemsetAsync(pwV,    0, sizeof(float) * NN * D);
    cudaMemsetAsync(pz,     0, sizeof(float) * NN * 8);
    cudaMemsetAsync(pstats, 0, sizeof(float) * 4 * 2 * D);

    // weight prep
    prep_w<<<64, 256>>>(Wq,  128, 128, pimg + oWq);
    prep_w<<<64, 256>>>(Wk,  128, 128, pimg + oWk);
    prep_w<<<64, 256>>>(Wv,  128, 128, pimg + oWv);
    prep_w<<<64, 256>>>(We,  128, 128, pimg + oWe);
    prep_w<<<64, 256>>>(Ohw, 128, 128, pimg + oOh);
    prep_w<<<64, 256>>>(Oew, 128, 128, pimg + oOe);
    prep_w<<<128, 256>>>(fhw1, 128, 256, pimg + oF1h);
    prep_w<<<128, 256>>>(few1, 128, 256, pimg + oF1e);
    prep_w<<<128, 256>>>(fhw2, 256, 128, pimg + oF2h);
    prep_w<<<128, 256>>>(few2, 256, 128, pimg + oF2e);

    const int gN = (NN + 127) / 128;   // 391
    const int gE = (NE + 127) / 128;   // 6250

    // projections
    kA<<<dim3(gN, 1), 256, SMEM>>>(h_in, pimg + oWq, nullptr, nullptr, nullptr, nullptr, pQ,  NN);
    kA<<<dim3(gN, 1), 256, SMEM>>>(h_in, pimg + oWk, nullptr, nullptr, nullptr, nullptr, pK,  NN);
    kA<<<dim3(gN, 1), 256, SMEM>>>(h_in, pimg + oWv, nullptr, nullptr, nullptr, nullptr, pV,  NN);
    kA<<<dim3(gE, 1), 256, SMEM>>>(e_in, pimg + oWe, nullptr, nullptr, nullptr, nullptr, ppe, NE);

    // edge attention + scatter
    edge_kernel<<<(NE + 7) / 8, 256>>>(src, dst);
    hattn_div<<<(NN * D + 255) / 256, 256>>>();

    // O projections + residual
    kB<<<dim3(gN, 1), 256, SMEM>>>(pwV, pimg + oOh, Ohb, h_in, nullptr, nullptr, ph2, NN);
    kB<<<dim3(gE, 1), 256, SMEM>>>(ppe, pimg + oOe, Oeb, e_in, nullptr, nullptr, pe2, NE);
    colstats<<<512, 256>>>(ph2, NN, pstats + 0 * 2 * D);
    colstats<<<512, 256>>>(pe2, NE, pstats + 1 * 2 * D);
    finalize_bn<<<1, D>>>(0, bn1hg, bn1hb, 1.f / NN);
    finalize_bn<<<1, D>>>(1, bn1eg, bn1eb, 1.f / NE);

    // FFN h
    kC<<<dim3(gN, 2), 256, SMEM>>>(ph2,  pimg + oF1h, fhb1, nullptr, pbnab + 0 * 2 * D, nullptr, pmid, NN);
    kD<<<dim3(gN, 1), 256, SMEM>>>(pmid, pimg + oF2h, fhb2, ph2, nullptr, pbnab + 0 * 2 * D, outh, NN);
    // FFN e
    kC<<<dim3(gE, 2), 256, SMEM>>>(pe2,  pimg + oF1e, feb1, nullptr, pbnab + 1 * 2 * D, nullptr, pmid, NE);
    kD<<<dim3(gE, 1), 256, SMEM>>>(pmid, pimg + oF2e, feb2, pe2, nullptr, pbnab + 1 * 2 * D, oute, NE);

    colstats<<<512, 256>>>(outh, NN, pstats + 2 * 2 * D);
    colstats<<<512, 256>>>(oute, NE, pstats + 3 * 2 * D);
    finalize_bn<<<1, D>>>(2, bn2hg, bn2hb, 1.f / NN);
    finalize_bn<<<1, D>>>(3, bn2eg, bn2eb, 1.f / NE);

    out_norm<<<(int)(((size_t)(NN + NE) * D + 255) / 256), 256>>>(out);
}

// round 4
// speedup vs baseline: 2.7284x; 1.0407x over previous
#include <cuda_runtime.h>
#include <cuda_bf16.h>
#include <math.h>
#include <stdint.h>

#define NN 50000
#define NE 800000
#define D  128

// ---------------- scratch ----------------
static __device__ float g_Q  [NN * D];
static __device__ float g_Kb [NN * D];
static __device__ float g_V  [NN * D];
static __device__ float g_wV [NN * D];
static __device__ float g_z  [NN * 8];
static __device__ float g_h2 [NN * D];
static __device__ float g_pe [(size_t)NE * D];
static __device__ float g_e2 [(size_t)NE * D];
static __device__ float g_mid[(size_t)NE * 256];
static __device__ float g_stats[4 * 2 * D];
static __device__ float g_bnab [4 * 2 * D];
static __device__ __nv_bfloat16 g_wimg[458752];   // fragment-ordered bf16 hi/lo weight images

// ---------------- weight prep ----------------
// W[K,N] fp32 -> b-fragment-ordered bf16 image, hi/lo packed per fragment:
// uint4 slot idx4 = (kstep*(N/8) + ntile)*32 + lane holds {hi_reg0, hi_reg1, lo_reg0, lo_reg1}
__global__ void prep_w(const float* __restrict__ W, int K, int N, __nv_bfloat16* __restrict__ img)
{
    int idx = blockIdx.x * blockDim.x + threadIdx.x;
    if (idx >= K * N) return;
    int k = idx / N, n = idx - k * N;
    float w = __ldg(W + idx);
    __nv_bfloat16 hi = __float2bfloat16(w);
    __nv_bfloat16 lo = __float2bfloat16(w - __bfloat162float(hi));
    int kstep = k >> 4, kin = k & 15;
    int reg  = (kin >> 3) & 1;
    int tid4 = (kin >> 1) & 3;
    int p    = kin & 1;
    int gg   = n & 7;
    int ntile = n >> 3;
    int lane = gg * 4 + tid4;
    size_t idx4 = ((size_t)kstep * (N >> 3) + ntile) * 32 + lane;
    img[idx4 * 8 + reg * 2 + p]     = hi;
    img[idx4 * 8 + 4 + reg * 2 + p] = lo;
}

// ---------------- mma.sync bf16-split GEMM ----------------
__device__ __forceinline__ void mma16816(float* c, const uint32_t* a, uint32_t b0, uint32_t b1)
{
    asm volatile(
        "mma.sync.aligned.m16n8k16.row.col.f32.bf16.bf16.f32 "
        "{%0,%1,%2,%3}, {%4,%5,%6,%7}, {%8,%9}, {%0,%1,%2,%3};"
        : "+f"(c[0]), "+f"(c[1]), "+f"(c[2]), "+f"(c[3])
        : "r"(a[0]), "r"(a[1]), "r"(a[2]), "r"(a[3]), "r"(b0), "r"(b1));
}

// C[M,NT] = epi( X[M,KT] @ W ), block tile 128x128, grid = (NT/128, ceil(M/128))
template<int KT, int NT, int BN_IN, int RELU, int BIAS, int RESM, int DO_STATS, int DIVZ>
__global__ void __launch_bounds__(256)
mm_k(const float* __restrict__ X, const __nv_bfloat16* __restrict__ Wimg,
     const float* __restrict__ bias, const float* __restrict__ res,
     const float* __restrict__ in_ab, const float* __restrict__ res_ab,
     const float* __restrict__ zdiv, float* __restrict__ stats,
     float* __restrict__ C, int M)
{
    constexpr int SAP = 136;
    extern __shared__ __nv_bfloat16 sA[];
    __nv_bfloat16* Ah = sA;
    __nv_bfloat16* Al = sA + 128 * SAP;

    const int tid  = threadIdx.x;
    const int w    = tid >> 5, lane = tid & 31;
    const int wr   = w >> 1, wc = w & 1;
    const int g    = lane >> 2, tid4 = lane & 3;
    const int row0   = blockIdx.y * 128;
    const int ntile0 = blockIdx.x * 16;

    const uint4* Bimg = (const uint4*)Wimg;

    float acc[2][8][4];
    #pragma unroll
    for (int mt = 0; mt < 2; mt++)
        #pragma unroll
        for (int nt = 0; nt < 8; nt++)
            #pragma unroll
            for (int i = 0; i < 4; i++) acc[mt][nt][i] = 0.f;

    for (int kc = 0; kc < KT / 128; kc++) {
        #pragma unroll 4
        for (int i = tid; i < 4096; i += 256) {
            int r = i >> 5, c4 = i & 31, col = c4 * 4;
            float4 v = make_float4(0.f, 0.f, 0.f, 0.f);
            int gr = row0 + r;
            if (gr < M) {
                v = __ldg((const float4*)(X + (size_t)gr * KT + kc * 128) + c4);
                if (BN_IN) {
                    int kk = kc * 128 + col;
                    v.x = fmaf(v.x, __ldg(in_ab + kk + 0), __ldg(in_ab + KT + kk + 0));
                    v.y = fmaf(v.y, __ldg(in_ab + kk + 1), __ldg(in_ab + KT + kk + 1));
                    v.z = fmaf(v.z, __ldg(in_ab + kk + 2), __ldg(in_ab + KT + kk + 2));
                    v.w = fmaf(v.w, __ldg(in_ab + kk + 3), __ldg(in_ab + KT + kk + 3));
                }
                if (DIVZ) {
                    float inv = 1.0f / (__ldg(zdiv + gr * 8 + (c4 >> 2)) + 1e-6f);
                    v.x *= inv; v.y *= inv; v.z *= inv; v.w *= inv;
                }
            }
            __nv_bfloat162 h0 = __floats2bfloat162_rn(v.x, v.y);
            __nv_bfloat162 h1 = __floats2bfloat162_rn(v.z, v.w);
            __nv_bfloat162 l0 = __floats2bfloat162_rn(v.x - __bfloat162float(h0.x),
                                                      v.y - __bfloat162float(h0.y));
            __nv_bfloat162 l1 = __floats2bfloat162_rn(v.z - __bfloat162float(h1.x),
                                                      v.w - __bfloat162float(h1.y));
            *(__nv_bfloat162*)(Ah + r * SAP + col)     = h0;
            *(__nv_bfloat162*)(Ah + r * SAP + col + 2) = h1;
            *(__nv_bfloat162*)(Al + r * SAP + col)     = l0;
            *(__nv_bfloat162*)(Al + r * SAP + col + 2) = l1;
        }
        __syncthreads();

        #pragma unroll
        for (int ks = 0; ks < 8; ks++) {
            const int gks = kc * 8 + ks;
            // B fragments: one LDG.128 per ntile (hi+lo packed)
            uint4 b[8];
            #pragma unroll
            for (int nt = 0; nt < 8; nt++)
                b[nt] = __ldg(Bimg + ((size_t)gks * (NT / 8) + (ntile0 + wc * 8 + nt)) * 32 + lane);

            uint32_t ah[2][4], al[2][4];
            #pragma unroll
            for (int mt = 0; mt < 2; mt++) {
                int r0 = wr * 32 + mt * 16 + g;
                int kk = ks * 16 + tid4 * 2;
                ah[mt][0] = *(const uint32_t*)(Ah + (r0    ) * SAP + kk);
                ah[mt][1] = *(const uint32_t*)(Ah + (r0 + 8) * SAP + kk);
                ah[mt][2] = *(const uint32_t*)(Ah + (r0    ) * SAP + kk + 8);
                ah[mt][3] = *(const uint32_t*)(Ah + (r0 + 8) * SAP + kk + 8);
                al[mt][0] = *(const uint32_t*)(Al + (r0    ) * SAP + kk);
                al[mt][1] = *(const uint32_t*)(Al + (r0 + 8) * SAP + kk);
                al[mt][2] = *(const uint32_t*)(Al + (r0    ) * SAP + kk + 8);
                al[mt][3] = *(const uint32_t*)(Al + (r0 + 8) * SAP + kk + 8);
            }
            #pragma unroll
            for (int nt = 0; nt < 8; nt++) {
                #pragma unroll
                for (int mt = 0; mt < 2; mt++) mma16816(acc[mt][nt], ah[mt], b[nt].x, b[nt].y);
                #pragma unroll
                for (int mt = 0; mt < 2; mt++) mma16816(acc[mt][nt], ah[mt], b[nt].z, b[nt].w);
                #pragma unroll
                for (int mt = 0; mt < 2; mt++) mma16816(acc[mt][nt], al[mt], b[nt].x, b[nt].y);
            }
        }
        __syncthreads();
    }

    // ---- epilogue ----
    float s1[16], s2[16];
    if (DO_STATS) {
        #pragma unroll
        for (int j = 0; j < 16; j++) { s1[j] = 0.f; s2[j] = 0.f; }
    }
    #pragma unroll
    for (int mt = 0; mt < 2; mt++) {
        #pragma unroll
        for (int half = 0; half < 2; half++) {
            int gr = row0 + wr * 32 + mt * 16 + g + half * 8;
            if (gr >= M) continue;
            #pragma unroll
            for (int nt = 0; nt < 8; nt++) {
                int col = blockIdx.x * 128 + wc * 64 + nt * 8 + tid4 * 2;
                float o0 = acc[mt][nt][half * 2 + 0];
                float o1 = acc[mt][nt][half * 2 + 1];
                if (BIAS) { o0 += __ldg(bias + col); o1 += __ldg(bias + col + 1); }
                if (RESM) {
                    float2 rv = __ldg((const float2*)(res + (size_t)gr * NT + col));
                    if (RESM == 1) { o0 += rv.x; o1 += rv.y; }
                    else {
                        o0 = fmaf(rv.x, __ldg(res_ab + col),     o0 + __ldg(res_ab + NT + col));
                        o1 = fmaf(rv.y, __ldg(res_ab + col + 1), o1 + __ldg(res_ab + NT + col + 1));
                    }
                }
                if (RELU) { o0 = fmaxf(o0, 0.f); o1 = fmaxf(o1, 0.f); }
                if (DO_STATS) {
                    s1[nt * 2 + 0] += o0; s2[nt * 2 + 0] = fmaf(o0, o0, s2[nt * 2 + 0]);
                    s1[nt * 2 + 1] += o1; s2[nt * 2 + 1] = fmaf(o1, o1, s2[nt * 2 + 1]);
                }
                *(float2*)(C + (size_t)gr * NT + col) = make_float2(o0, o1);
            }
        }
    }
    if (DO_STATS) {
        #pragma unroll
        for (int j = 0; j < 16; j++) {
            float a = s1[j], q = s2[j];
            a += __shfl_xor_sync(0xffffffffu, a, 4);  q += __shfl_xor_sync(0xffffffffu, q, 4);
            a += __shfl_xor_sync(0xffffffffu, a, 8);  q += __shfl_xor_sync(0xffffffffu, q, 8);
            a += __shfl_xor_sync(0xffffffffu, a, 16); q += __shfl_xor_sync(0xffffffffu, q, 16);
            if (g == 0) {
                int col = wc * 64 + (j >> 1) * 8 + tid4 * 2 + (j & 1);
                atomicAdd(stats + col, a);
                atomicAdd(stats + 128 + col, q);
            }
        }
    }
}

// ---------------- edge attention ----------------
__global__ void edge_kernel(const int* __restrict__ src, const int* __restrict__ dst)
{
    int w    = (blockIdx.x * blockDim.x + threadIdx.x) >> 5;
    int lane = threadIdx.x & 31;
    if (w >= NE) return;
    int s = __ldg(src + w), d = __ldg(dst + w);

    float4 q = __ldg(reinterpret_cast<const float4*>(g_Q  + (size_t)d * D) + lane);
    float4 k = __ldg(reinterpret_cast<const float4*>(g_Kb + (size_t)s * D) + lane);
    float4 p = *(reinterpret_cast<const float4*>(g_pe + (size_t)w * D) + lane);

    float4 sc;
    sc.x = k.x * q.x * 0.25f * p.x;
    sc.y = k.y * q.y * 0.25f * p.y;
    sc.z = k.z * q.z * 0.25f * p.z;
    sc.w = k.w * q.w * 0.25f * p.w;
    *(reinterpret_cast<float4*>(g_pe + (size_t)w * D) + lane) = sc;

    float part = sc.x + sc.y + sc.z + sc.w;
    part += __shfl_xor_sync(0xffffffffu, part, 1);
    part += __shfl_xor_sync(0xffffffffu, part, 2);
    part  = fminf(fmaxf(part, -5.f), 5.f);
    float sh = expf(part);

    float4 v = __ldg(reinterpret_cast<const float4*>(g_V + (size_t)s * D) + lane);
    float* wv = g_wV + (size_t)d * D + lane * 4;
    asm volatile("red.global.add.v4.f32 [%0], {%1, %2, %3, %4};"
                 :: "l"(wv), "f"(v.x * sh), "f"(v.y * sh), "f"(v.z * sh), "f"(v.w * sh)
                 : "memory");
    if ((lane & 3) == 0) atomicAdd(g_z + (size_t)d * 8 + (lane >> 2), sh);
}

__global__ void finalize_bn(int bn, const float* __restrict__ g, const float* __restrict__ b, float minv)
{
    int c = threadIdx.x;
    float mean = g_stats[bn * 2 * D + c] * minv;
    float var  = g_stats[bn * 2 * D + D + c] * minv - mean * mean;
    float rstd = rsqrtf(var + 1e-5f);
    float scv  = g[c] * rstd;
    g_bnab[bn * 2 * D + c]     = scv;
    g_bnab[bn * 2 * D + D + c] = b[c] - mean * scv;
}

__global__ void out_norm(float* __restrict__ out)
{
    size_t i = (size_t)blockIdx.x * blockDim.x + threadIdx.x;
    if (i < (size_t)(NN + NE) * D) {
        int c  = (int)(i & 127);
        int bn = (i < (size_t)NN * D) ? 2 : 3;
        out[i] = fmaf(out[i], g_bnab[bn * 2 * D + c], g_bnab[bn * 2 * D + D + c]);
    }
}

// ---------------- host ----------------
extern "C" void kernel_launch(void* const* d_in, const int* in_sizes, int n_in,
                              void* d_out, int out_size)
{
    (void)in_sizes; (void)n_in; (void)out_size;
    const float* h_in  = (const float*)d_in[0];
    const float* e_in  = (const float*)d_in[1];
    const float* Wq    = (const float*)d_in[2];
    const float* Wk    = (const float*)d_in[3];
    const float* Wv    = (const float*)d_in[4];
    const float* We    = (const float*)d_in[5];
    const float* Ohw   = (const float*)d_in[6];
    const float* Ohb   = (const float*)d_in[7];
    const float* Oew   = (const float*)d_in[8];
    const float* Oeb   = (const float*)d_in[9];
    const float* bn1hg = (const float*)d_in[10];
    const float* bn1hb = (const float*)d_in[11];
    const float* bn1eg = (const float*)d_in[12];
    const float* bn1eb = (const float*)d_in[13];
    const float* fhw1  = (const float*)d_in[14];
    const float* fhb1  = (const float*)d_in[15];
    const float* fhw2  = (const float*)d_in[16];
    const float* fhb2  = (const float*)d_in[17];
    const float* few1  = (const float*)d_in[18];
    const float* feb1  = (const float*)d_in[19];
    const float* few2  = (const float*)d_in[20];
    const float* feb2  = (const float*)d_in[21];
    const float* bn2hg = (const float*)d_in[22];
    const float* bn2hb = (const float*)d_in[23];
    const float* bn2eg = (const float*)d_in[24];
    const float* bn2eb = (const float*)d_in[25];
    const int*   src   = (const int*)d_in[26];
    const int*   dst   = (const int*)d_in[27];

    float* out  = (float*)d_out;
    float* outh = out;
    float* oute = out + (size_t)NN * D;

    float *pQ, *pK, *pV, *ppe, *pwV, *pz, *ph2, *pe2, *pmid, *pstats, *pbnab;
    __nv_bfloat16* pimg;
    cudaGetSymbolAddress((void**)&pQ,    g_Q);
    cudaGetSymbolAddress((void**)&pK,    g_Kb);
    cudaGetSymbolAddress((void**)&pV,    g_V);
    cudaGetSymbolAddress((void**)&ppe,   g_pe);
    cudaGetSymbolAddress((void**)&pwV,   g_wV);
    cudaGetSymbolAddress((void**)&pz,    g_z);
    cudaGetSymbolAddress((void**)&ph2,   g_h2);
    cudaGetSymbolAddress((void**)&pe2,   g_e2);
    cudaGetSymbolAddress((void**)&pmid,  g_mid);
    cudaGetSymbolAddress((void**)&pstats, g_stats);
    cudaGetSymbolAddress((void**)&pbnab,  g_bnab);
    cudaGetSymbolAddress((void**)&pimg,   g_wimg);

    const size_t oWq = 32768, oWk = 65536, oWv = 98304, oWe = 0;
    const size_t oOh = 131072, oOe = 163840;
    const size_t oF1h = 196608, oF1e = 262144, oF2h = 327680, oF2e = 393216;

    auto kA  = mm_k<128, 128, 0, 0, 0, 0, 0, 0>;  // plain
    auto kBh = mm_k<128, 128, 0, 0, 1, 1, 1, 1>;  // +bias +res +stats +divz
    auto kBe = mm_k<128, 128, 0, 0, 1, 1, 1, 0>;  // +bias +res +stats
    auto kC  = mm_k<128, 256, 1, 1, 1, 0, 0, 0>;  // BN(in) -> relu
    auto kD  = mm_k<256, 128, 0, 0, 1, 2, 1, 0>;  // +bias +BN(res) +stats

    const int SMEM = 2 * 128 * 136 * 2;
    cudaFuncSetAttribute(kA,  cudaFuncAttributeMaxDynamicSharedMemorySize, SMEM);
    cudaFuncSetAttribute(kBh, cudaFuncAttributeMaxDynamicSharedMemorySize, SMEM);
    cudaFuncSetAttribute(kBe, cudaFuncAttributeMaxDynamicSharedMemorySize, SMEM);
    cudaFuncSetAttribute(kC,  cudaFuncAttributeMaxDynamicSharedMemorySize, SMEM);
    cudaFuncSetAttribute(kD,  cudaFuncAttributeMaxDynamicSharedMemorySize, SMEM);

    const int gN = (NN + 127) / 128;   // 391
    const int gE = (NE + 127) / 128;   // 6250

    // launches 1-5: weight preps needed first (keeps big GEMM at launch #6 for ncu)
    prep_w<<<64, 256>>>(We,  128, 128, pimg + oWe);
    prep_w<<<64, 256>>>(Wq,  128, 128, pimg + oWq);
    prep_w<<<64, 256>>>(Wk,  128, 128, pimg + oWk);
    prep_w<<<64, 256>>>(Wv,  128, 128, pimg + oWv);
    prep_w<<<64, 256>>>(Ohw, 128, 128, pimg + oOh);
    // launch 6: the big e-side projection GEMM (ncu sample target)
    kA<<<dim3(1, gE), 256, SMEM>>>(e_in, pimg + oWe, nullptr, nullptr, nullptr, nullptr, nullptr, nullptr, ppe, NE);

    prep_w<<<64, 256>>>(Oew, 128, 128, pimg + oOe);
    prep_w<<<128, 256>>>(fhw1, 128, 256, pimg + oF1h);
    prep_w<<<128, 256>>>(few1, 128, 256, pimg + oF1e);
    prep_w<<<128, 256>>>(fhw2, 256, 128, pimg + oF2h);
    prep_w<<<128, 256>>>(few2, 256, 128, pimg + oF2e);

    cudaMemsetAsync(pwV,    0, sizeof(float) * NN * D);
    cudaMemsetAsync(pz,     0, sizeof(float) * NN * 8);
    cudaMemsetAsync(pstats, 0, sizeof(float) * 4 * 2 * D);

    // node projections
    kA<<<dim3(1, gN), 256, SMEM>>>(h_in, pimg + oWq, nullptr, nullptr, nullptr, nullptr, nullptr, nullptr, pQ, NN);
    kA<<<dim3(1, gN), 256, SMEM>>>(h_in, pimg + oWk, nullptr, nullptr, nullptr, nullptr, nullptr, nullptr, pK, NN);
    kA<<<dim3(1, gN), 256, SMEM>>>(h_in, pimg + oWv, nullptr, nullptr, nullptr, nullptr, nullptr, nullptr, pV, NN);

    // edge attention + scatter
    edge_kernel<<<(NE + 7) / 8, 256>>>(src, dst);

    // O projections + residual + fused bn1 stats (+ z-divide for h side)
    kBh<<<dim3(1, gN), 256, SMEM>>>(pwV, pimg + oOh, Ohb, h_in, nullptr, nullptr, pz, pstats + 0 * 2 * D, ph2, NN);
    kBe<<<dim3(1, gE), 256, SMEM>>>(ppe, pimg + oOe, Oeb, e_in, nullptr, nullptr, nullptr, pstats + 1 * 2 * D, pe2, NE);
    finalize_bn<<<1, D>>>(0, bn1hg, bn1hb, 1.f / NN);
    finalize_bn<<<1, D>>>(1, bn1eg, bn1eb, 1.f / NE);

    // FFN h
    kC<<<dim3(2, gN), 256, SMEM>>>(ph2,  pimg + oF1h, fhb1, nullptr, pbnab + 0 * 2 * D, nullptr, nullptr, nullptr, pmid, NN);
    kD<<<dim3(1, gN), 256, SMEM>>>(pmid, pimg + oF2h, fhb2, ph2, nullptr, pbnab + 0 * 2 * D, nullptr, pstats + 2 * 2 * D, outh, NN);
    // FFN e
    kC<<<dim3(2, gE), 256, SMEM>>>(pe2,  pimg + oF1e, feb1, nullptr, pbnab + 1 * 2 * D, nullptr, nullptr, nullptr, pmid, NE);
    kD<<<dim3(1, gE), 256, SMEM>>>(pmid, pimg + oF2e, feb2, pe2, nullptr, pbnab + 1 * 2 * D, nullptr, pstats + 3 * 2 * D, oute, NE);

    finalize_bn<<<1, D>>>(2, bn2hg, bn2hb, 1.f / NN);
    finalize_bn<<<1, D>>>(3, bn2eg, bn2eb, 1.f / NE);

    out_norm<<<(int)(((size_t)(NN + NE) * D + 255) / 256), 256>>>(out);
}

// round 5
// speedup vs baseline: 3.0683x; 1.1246x over previous
#include <cuda_runtime.h>
#include <cuda_bf16.h>
#include <math.h>
#include <stdint.h>

#define NN 50000
#define NE 800000
#define D  128

// ---------------- scratch ----------------
static __device__ float g_Q  [NN * D];
static __device__ float g_Kb [NN * D];
static __device__ float g_V  [NN * D];
static __device__ float g_wV [NN * D];
static __device__ float g_z  [NN * 8];
static __device__ float g_h2 [NN * D];
static __device__ float g_pe [(size_t)NE * D];   // e_attn_out (score)
static __device__ float g_e2 [(size_t)NE * D];
static __device__ float g_stats[4 * 2 * D];
static __device__ float g_bnab [4 * 2 * D];
static __device__ __nv_bfloat16 g_wimg[458752];

// ---------------- weight prep (fragment-ordered, hi/lo packed per uint4) ----------------
__global__ void prep_w(const float* __restrict__ W, int K, int N, __nv_bfloat16* __restrict__ img)
{
    int idx = blockIdx.x * blockDim.x + threadIdx.x;
    if (idx >= K * N) return;
    int k = idx / N, n = idx - k * N;
    float w = __ldg(W + idx);
    __nv_bfloat16 hi = __float2bfloat16(w);
    __nv_bfloat16 lo = __float2bfloat16(w - __bfloat162float(hi));
    int kstep = k >> 4, kin = k & 15;
    int reg  = (kin >> 3) & 1;
    int tid4 = (kin >> 1) & 3;
    int p    = kin & 1;
    int gg   = n & 7;
    int ntile = n >> 3;
    int lane = gg * 4 + tid4;
    size_t idx4 = ((size_t)kstep * (N >> 3) + ntile) * 32 + lane;
    img[idx4 * 8 + reg * 2 + p]     = hi;
    img[idx4 * 8 + 4 + reg * 2 + p] = lo;
}

__device__ __forceinline__ void mma16816(float* c, const uint32_t* a, uint32_t b0, uint32_t b1)
{
    asm volatile(
        "mma.sync.aligned.m16n8k16.row.col.f32.bf16.bf16.f32 "
        "{%0,%1,%2,%3}, {%4,%5,%6,%7}, {%8,%9}, {%0,%1,%2,%3};"
        : "+f"(c[0]), "+f"(c[1]), "+f"(c[2]), "+f"(c[3])
        : "r"(a[0]), "r"(a[1]), "r"(a[2]), "r"(a[3]), "r"(b0), "r"(b1));
}

__device__ __forceinline__ void split_store(__nv_bfloat16* Ah, __nv_bfloat16* Al,
                                            int off, float4 v)
{
    __nv_bfloat162 h0 = __floats2bfloat162_rn(v.x, v.y);
    __nv_bfloat162 h1 = __floats2bfloat162_rn(v.z, v.w);
    __nv_bfloat162 l0 = __floats2bfloat162_rn(v.x - __bfloat162float(h0.x),
                                              v.y - __bfloat162float(h0.y));
    __nv_bfloat162 l1 = __floats2bfloat162_rn(v.z - __bfloat162float(h1.x),
                                              v.w - __bfloat162float(h1.y));
    *(__nv_bfloat162*)(Ah + off)     = h0;
    *(__nv_bfloat162*)(Ah + off + 2) = h1;
    *(__nv_bfloat162*)(Al + off)     = l0;
    *(__nv_bfloat162*)(Al + off + 2) = l1;
}

// ---------------- generic 128x128 GEMM (+optional fused edge attention) ----------------
// grid = (1, ceil(M/128)); 256 threads
template<int BN_IN, int RELU, int BIAS, int RESM, int DO_STATS, int DIVZ, int EDGE>
__global__ void __launch_bounds__(256)
mm_k(const float* __restrict__ X, const __nv_bfloat16* __restrict__ Wimg,
     const float* __restrict__ bias, const float* __restrict__ res,
     const float* __restrict__ in_ab, const float* __restrict__ res_ab,
     const float* __restrict__ zdiv, float* __restrict__ stats,
     const int* __restrict__ src, const int* __restrict__ dst,
     float* __restrict__ C, int M)
{
    constexpr int SAP = 136;
    extern __shared__ __nv_bfloat16 sA[];
    __nv_bfloat16* Ah = sA;
    __nv_bfloat16* Al = sA + 128 * SAP;

    const int tid  = threadIdx.x;
    const int w    = tid >> 5, lane = tid & 31;
    const int wr   = w >> 1, wc = w & 1;
    const int g    = lane >> 2, tid4 = lane & 3;
    const int row0 = blockIdx.y * 128;

    const uint4* Bimg = (const uint4*)Wimg;

    float acc[2][8][4];
    #pragma unroll
    for (int mt = 0; mt < 2; mt++)
        #pragma unroll
        for (int nt = 0; nt < 8; nt++)
            #pragma unroll
            for (int i = 0; i < 4; i++) acc[mt][nt][i] = 0.f;

    // ---- stage A ----
    #pragma unroll 4
    for (int i = tid; i < 4096; i += 256) {
        int r = i >> 5, c4 = i & 31, col = c4 * 4;
        float4 v = make_float4(0.f, 0.f, 0.f, 0.f);
        int gr = row0 + r;
        if (gr < M) {
            v = __ldg((const float4*)(X + (size_t)gr * 128) + c4);
            if (BN_IN) {
                v.x = fmaf(v.x, __ldg(in_ab + col + 0), __ldg(in_ab + 128 + col + 0));
                v.y = fmaf(v.y, __ldg(in_ab + col + 1), __ldg(in_ab + 128 + col + 1));
                v.z = fmaf(v.z, __ldg(in_ab + col + 2), __ldg(in_ab + 128 + col + 2));
                v.w = fmaf(v.w, __ldg(in_ab + col + 3), __ldg(in_ab + 128 + col + 3));
            }
            if (DIVZ) {
                float inv = 1.0f / (__ldg(zdiv + gr * 8 + (c4 >> 2)) + 1e-6f);
                v.x *= inv; v.y *= inv; v.z *= inv; v.w *= inv;
            }
        }
        split_store(Ah, Al, r * SAP + col, v);
    }
    __syncthreads();

    // ---- MMA mainloop (K=128) ----
    #pragma unroll
    for (int ks = 0; ks < 8; ks++) {
        uint4 b[8];
        #pragma unroll
        for (int nt = 0; nt < 8; nt++)
            b[nt] = __ldg(Bimg + ((size_t)ks * 16 + (wc * 8 + nt)) * 32 + lane);
        uint32_t ah[2][4], al[2][4];
        #pragma unroll
        for (int mt = 0; mt < 2; mt++) {
            int r0 = wr * 32 + mt * 16 + g;
            int kk = ks * 16 + tid4 * 2;
            ah[mt][0] = *(const uint32_t*)(Ah + (r0    ) * SAP + kk);
            ah[mt][1] = *(const uint32_t*)(Ah + (r0 + 8) * SAP + kk);
            ah[mt][2] = *(const uint32_t*)(Ah + (r0    ) * SAP + kk + 8);
            ah[mt][3] = *(const uint32_t*)(Ah + (r0 + 8) * SAP + kk + 8);
            al[mt][0] = *(const uint32_t*)(Al + (r0    ) * SAP + kk);
            al[mt][1] = *(const uint32_t*)(Al + (r0 + 8) * SAP + kk);
            al[mt][2] = *(const uint32_t*)(Al + (r0    ) * SAP + kk + 8);
            al[mt][3] = *(const uint32_t*)(Al + (r0 + 8) * SAP + kk + 8);
        }
        #pragma unroll
        for (int nt = 0; nt < 8; nt++) {
            #pragma unroll
            for (int mt = 0; mt < 2; mt++) mma16816(acc[mt][nt], ah[mt], b[nt].x, b[nt].y);
            #pragma unroll
            for (int mt = 0; mt < 2; mt++) mma16816(acc[mt][nt], ah[mt], b[nt].z, b[nt].w);
            #pragma unroll
            for (int mt = 0; mt < 2; mt++) mma16816(acc[mt][nt], al[mt], b[nt].x, b[nt].y);
        }
    }
    __syncthreads();

    if (EDGE) {
        // park pe tile in smem, then per-warp edge attention
        float* P = (float*)sA;   // 128 x 132 floats = 67584 B
        #pragma unroll
        for (int mt = 0; mt < 2; mt++)
            #pragma unroll
            for (int half = 0; half < 2; half++) {
                int rl = wr * 32 + mt * 16 + g + half * 8;
                #pragma unroll
                for (int nt = 0; nt < 8; nt++) {
                    int col = wc * 64 + nt * 8 + tid4 * 2;
                    *(float2*)(P + rl * 132 + col) =
                        make_float2(acc[mt][nt][half * 2 + 0], acc[mt][nt][half * 2 + 1]);
                }
            }
        __syncthreads();
        for (int i = 0; i < 16; i++) {
            int rl = w * 16 + i;
            int er = row0 + rl;
            if (er >= M) break;
            int s = __ldg(src + er), d = __ldg(dst + er);
            float4 p = *(float4*)(P + rl * 132 + lane * 4);
            float4 q = __ldg((const float4*)(g_Q  + (size_t)d * D) + lane);
            float4 k = __ldg((const float4*)(g_Kb + (size_t)s * D) + lane);
            float4 sc;
            sc.x = k.x * q.x * 0.25f * p.x;
            sc.y = k.y * q.y * 0.25f * p.y;
            sc.z = k.z * q.z * 0.25f * p.z;
            sc.w = k.w * q.w * 0.25f * p.w;
            *((float4*)(C + (size_t)er * D) + lane) = sc;   // e_attn_out
            float part = sc.x + sc.y + sc.z + sc.w;
            part += __shfl_xor_sync(0xffffffffu, part, 1);
            part += __shfl_xor_sync(0xffffffffu, part, 2);
            part  = fminf(fmaxf(part, -5.f), 5.f);
            float sh = expf(part);
            float4 v = __ldg((const float4*)(g_V + (size_t)s * D) + lane);
            float* wv = g_wV + (size_t)d * D + lane * 4;
            asm volatile("red.global.add.v4.f32 [%0], {%1, %2, %3, %4};"
                         :: "l"(wv), "f"(v.x * sh), "f"(v.y * sh), "f"(v.z * sh), "f"(v.w * sh)
                         : "memory");
            if ((lane & 3) == 0) atomicAdd(g_z + (size_t)d * 8 + (lane >> 2), sh);
        }
        return;
    }

    // ---- standard epilogue ----
    float s1[16], s2[16];
    if (DO_STATS) {
        #pragma unroll
        for (int j = 0; j < 16; j++) { s1[j] = 0.f; s2[j] = 0.f; }
    }
    #pragma unroll
    for (int mt = 0; mt < 2; mt++)
        #pragma unroll
        for (int half = 0; half < 2; half++) {
            int gr = row0 + wr * 32 + mt * 16 + g + half * 8;
            if (gr >= M) continue;
            #pragma unroll
            for (int nt = 0; nt < 8; nt++) {
                int col = wc * 64 + nt * 8 + tid4 * 2;
                float o0 = acc[mt][nt][half * 2 + 0];
                float o1 = acc[mt][nt][half * 2 + 1];
                if (BIAS) { o0 += __ldg(bias + col); o1 += __ldg(bias + col + 1); }
                if (RESM) {
                    float2 rv = __ldg((const float2*)(res + (size_t)gr * D + col));
                    if (RESM == 1) { o0 += rv.x; o1 += rv.y; }
                    else {
                        o0 = fmaf(rv.x, __ldg(res_ab + col),     o0 + __ldg(res_ab + 128 + col));
                        o1 = fmaf(rv.y, __ldg(res_ab + col + 1), o1 + __ldg(res_ab + 128 + col + 1));
                    }
                }
                if (RELU) { o0 = fmaxf(o0, 0.f); o1 = fmaxf(o1, 0.f); }
                if (DO_STATS) {
                    s1[nt * 2 + 0] += o0; s2[nt * 2 + 0] = fmaf(o0, o0, s2[nt * 2 + 0]);
                    s1[nt * 2 + 1] += o1; s2[nt * 2 + 1] = fmaf(o1, o1, s2[nt * 2 + 1]);
                }
                *(float2*)(C + (size_t)gr * D + col) = make_float2(o0, o1);
            }
        }
    if (DO_STATS) {
        #pragma unroll
        for (int j = 0; j < 16; j++) {
            float a = s1[j], q = s2[j];
            a += __shfl_xor_sync(0xffffffffu, a, 4);  q += __shfl_xor_sync(0xffffffffu, q, 4);
            a += __shfl_xor_sync(0xffffffffu, a, 8);  q += __shfl_xor_sync(0xffffffffu, q, 8);
            a += __shfl_xor_sync(0xffffffffu, a, 16); q += __shfl_xor_sync(0xffffffffu, q, 16);
            if (g == 0) {
                int col = wc * 64 + (j >> 1) * 8 + tid4 * 2 + (j & 1);
                atomicAdd(stats + col, a);
                atomicAdd(stats + 128 + col, q);
            }
        }
    }
}

// ---------------- fused FFN: C = BN_res( relu(BN(X)@W1+b1)@W2 + b2 + BN(X) ), + stats ----------------
// 512 threads, grid = (ceil(M/128)); smem: mid tile 128x264 hi/lo (A staged in same buffer first)
__global__ void __launch_bounds__(512)
ffn_k(const float* __restrict__ X, const __nv_bfloat16* __restrict__ W1img,
      const float* __restrict__ b1, const __nv_bfloat16* __restrict__ W2img,
      const float* __restrict__ b2, const float* __restrict__ bnab,
      float* __restrict__ stats, float* __restrict__ C, int M)
{
    constexpr int SAP = 136, MP = 264;
    extern __shared__ __nv_bfloat16 sm[];
    __nv_bfloat16* Ah = sm;
    __nv_bfloat16* Al = sm + 128 * SAP;
    __nv_bfloat16* Mh = sm;
    __nv_bfloat16* Ml = sm + 128 * MP;

    const int tid  = threadIdx.x;
    const int w    = tid >> 5, lane = tid & 31;
    const int wr   = w >> 2, wc = w & 3;           // 4x4 warp grid
    const int g    = lane >> 2, tid4 = lane & 3;
    const int row0 = blockIdx.x * 128;

    const uint4* B1 = (const uint4*)W1img;
    const uint4* B2 = (const uint4*)W2img;

    // ---- stage A = BN(X) ----
    #pragma unroll 2
    for (int i = tid; i < 4096; i += 512) {
        int r = i >> 5, c4 = i & 31, col = c4 * 4;
        float4 v = make_float4(0.f, 0.f, 0.f, 0.f);
        int gr = row0 + r;
        if (gr < M) {
            v = __ldg((const float4*)(X + (size_t)gr * 128) + c4);
            v.x = fmaf(v.x, __ldg(bnab + col + 0), __ldg(bnab + 128 + col + 0));
            v.y = fmaf(v.y, __ldg(bnab + col + 1), __ldg(bnab + 128 + col + 1));
            v.z = fmaf(v.z, __ldg(bnab + col + 2), __ldg(bnab + 128 + col + 2));
            v.w = fmaf(v.w, __ldg(bnab + col + 3), __ldg(bnab + 128 + col + 3));
        }
        split_store(Ah, Al, r * SAP + col, v);
    }
    __syncthreads();

    // ---- FFN1: 128x256, warp tile 32x64 ----
    float acc1[2][8][4];
    #pragma unroll
    for (int mt = 0; mt < 2; mt++)
        #pragma unroll
        for (int nt = 0; nt < 8; nt++)
            #pragma unroll
            for (int i = 0; i < 4; i++) acc1[mt][nt][i] = 0.f;

    #pragma unroll
    for (int ks = 0; ks < 8; ks++) {
        uint32_t ah[2][4], al[2][4];
        #pragma unroll
        for (int mt = 0; mt < 2; mt++) {
            int r0 = wr * 32 + mt * 16 + g;
            int kk = ks * 16 + tid4 * 2;
            ah[mt][0] = *(const uint32_t*)(Ah + (r0    ) * SAP + kk);
            ah[mt][1] = *(const uint32_t*)(Ah + (r0 + 8) * SAP + kk);
            ah[mt][2] = *(const uint32_t*)(Ah + (r0    ) * SAP + kk + 8);
            ah[mt][3] = *(const uint32_t*)(Ah + (r0 + 8) * SAP + kk + 8);
            al[mt][0] = *(const uint32_t*)(Al + (r0    ) * SAP + kk);
            al[mt][1] = *(const uint32_t*)(Al + (r0 + 8) * SAP + kk);
            al[mt][2] = *(const uint32_t*)(Al + (r0    ) * SAP + kk + 8);
            al[mt][3] = *(const uint32_t*)(Al + (r0 + 8) * SAP + kk + 8);
        }
        #pragma unroll
        for (int nt = 0; nt < 8; nt++) {
            uint4 b = __ldg(B1 + ((size_t)ks * 32 + (wc * 8 + nt)) * 32 + lane);
            #pragma unroll
            for (int mt = 0; mt < 2; mt++) mma16816(acc1[mt][nt], ah[mt], b.x, b.y);
            #pragma unroll
            for (int mt = 0; mt < 2; mt++) mma16816(acc1[mt][nt], ah[mt], b.z, b.w);
            #pragma unroll
            for (int mt = 0; mt < 2; mt++) mma16816(acc1[mt][nt], al[mt], b.x, b.y);
        }
    }
    __syncthreads();   // done reading A

    // ---- mid = relu(acc1 + b1) -> smem hi/lo ----
    #pragma unroll
    for (int mt = 0; mt < 2; mt++)
        #pragma unroll
        for (int half = 0; half < 2; half++) {
            int rl = wr * 32 + mt * 16 + g + half * 8;
            #pragma unroll
            for (int nt = 0; nt < 8; nt++) {
                int col = wc * 64 + nt * 8 + tid4 * 2;
                float o0 = fmaxf(acc1[mt][nt][half * 2 + 0] + __ldg(b1 + col), 0.f);
                float o1 = fmaxf(acc1[mt][nt][half * 2 + 1] + __ldg(b1 + col + 1), 0.f);
                __nv_bfloat162 h = __floats2bfloat162_rn(o0, o1);
                __nv_bfloat162 l = __floats2bfloat162_rn(o0 - __bfloat162float(h.x),
                                                         o1 - __bfloat162float(h.y));
                *(__nv_bfloat162*)(Mh + rl * MP + col) = h;
                *(__nv_bfloat162*)(Ml + rl * MP + col) = l;
            }
        }
    __syncthreads();

    // ---- FFN2: 128x128, K=256, warp tile 32x32 ----
    float acc2[2][4][4];
    #pragma unroll
    for (int mt = 0; mt < 2; mt++)
        #pragma unroll
        for (int nt = 0; nt < 4; nt++)
            #pragma unroll
            for (int i = 0; i < 4; i++) acc2[mt][nt][i] = 0.f;

    #pragma unroll
    for (int ks = 0; ks < 16; ks++) {
        uint32_t ah[2][4], al[2][4];
        #pragma unroll
        for (int mt = 0; mt < 2; mt++) {
            int r0 = wr * 32 + mt * 16 + g;
            int kk = ks * 16 + tid4 * 2;
            ah[mt][0] = *(const uint32_t*)(Mh + (r0    ) * MP + kk);
            ah[mt][1] = *(const uint32_t*)(Mh + (r0 + 8) * MP + kk);
            ah[mt][2] = *(const uint32_t*)(Mh + (r0    ) * MP + kk + 8);
            ah[mt][3] = *(const uint32_t*)(Mh + (r0 + 8) * MP + kk + 8);
            al[mt][0] = *(const uint32_t*)(Ml + (r0    ) * MP + kk);
            al[mt][1] = *(const uint32_t*)(Ml + (r0 + 8) * MP + kk);
            al[mt][2] = *(const uint32_t*)(Ml + (r0    ) * MP + kk + 8);
            al[mt][3] = *(const uint32_t*)(Ml + (r0 + 8) * MP + kk + 8);
        }
        #pragma unroll
        for (int nt = 0; nt < 4; nt++) {
            uint4 b = __ldg(B2 + ((size_t)ks * 16 + (wc * 4 + nt)) * 32 + lane);
            #pragma unroll
            for (int mt = 0; mt < 2; mt++) mma16816(acc2[mt][nt], ah[mt], b.x, b.y);
            #pragma unroll
            for (int mt = 0; mt < 2; mt++) mma16816(acc2[mt][nt], ah[mt], b.z, b.w);
            #pragma unroll
            for (int mt = 0; mt < 2; mt++) mma16816(acc2[mt][nt], al[mt], b.x, b.y);
        }
    }

    // ---- epilogue: + b2 + BN(X residual), stats ----
    float s1[8], s2[8];
    #pragma unroll
    for (int j = 0; j < 8; j++) { s1[j] = 0.f; s2[j] = 0.f; }
    #pragma unroll
    for (int mt = 0; mt < 2; mt++)
        #pragma unroll
        for (int half = 0; half < 2; half++) {
            int gr = row0 + wr * 32 + mt * 16 + g + half * 8;
            if (gr >= M) continue;
            #pragma unroll
            for (int nt = 0; nt < 4; nt++) {
                int col = wc * 32 + nt * 8 + tid4 * 2;
                float o0 = acc2[mt][nt][half * 2 + 0] + __ldg(b2 + col);
                float o1 = acc2[mt][nt][half * 2 + 1] + __ldg(b2 + col + 1);
                float2 rv = __ldg((const float2*)(X + (size_t)gr * 128 + col));
                o0 = fmaf(rv.x, __ldg(bnab + col),     o0 + __ldg(bnab + 128 + col));
                o1 = fmaf(rv.y, __ldg(bnab + col + 1), o1 + __ldg(bnab + 128 + col + 1));
                s1[nt * 2 + 0] += o0; s2[nt * 2 + 0] = fmaf(o0, o0, s2[nt * 2 + 0]);
                s1[nt * 2 + 1] += o1; s2[nt * 2 + 1] = fmaf(o1, o1, s2[nt * 2 + 1]);
                *(float2*)(C + (size_t)gr * 128 + col) = make_float2(o0, o1);
            }
        }
    #pragma unroll
    for (int j = 0; j < 8; j++) {
        float a = s1[j], q = s2[j];
        a += __shfl_xor_sync(0xffffffffu, a, 4);  q += __shfl_xor_sync(0xffffffffu, q, 4);
        a += __shfl_xor_sync(0xffffffffu, a, 8);  q += __shfl_xor_sync(0xffffffffu, q, 8);
        a += __shfl_xor_sync(0xffffffffu, a, 16); q += __shfl_xor_sync(0xffffffffu, q, 16);
        if (g == 0) {
            int col = wc * 32 + (j >> 1) * 8 + tid4 * 2 + (j & 1);
            atomicAdd(stats + col, a);
            atomicAdd(stats + 128 + col, q);
        }
    }
}

__global__ void finalize_bn(int bn, const float* __restrict__ g, const float* __restrict__ b, float minv)
{
    int c = threadIdx.x;
    float mean = g_stats[bn * 2 * D + c] * minv;
    float var  = g_stats[bn * 2 * D + D + c] * minv - mean * mean;
    float rstd = rsqrtf(var + 1e-5f);
    float scv  = g[c] * rstd;
    g_bnab[bn * 2 * D + c]     = scv;
    g_bnab[bn * 2 * D + D + c] = b[c] - mean * scv;
}

__global__ void out_norm(float* __restrict__ out)
{
    size_t i = (size_t)blockIdx.x * blockDim.x + threadIdx.x;
    if (i < (size_t)(NN + NE) * D) {
        int c  = (int)(i & 127);
        int bn = (i < (size_t)NN * D) ? 2 : 3;
        out[i] = fmaf(out[i], g_bnab[bn * 2 * D + c], g_bnab[bn * 2 * D + D + c]);
    }
}

// ---------------- host ----------------
extern "C" void kernel_launch(void* const* d_in, const int* in_sizes, int n_in,
                              void* d_out, int out_size)
{
    (void)in_sizes; (void)n_in; (void)out_size;
    const float* h_in  = (const float*)d_in[0];
    const float* e_in  = (const float*)d_in[1];
    const float* Wq    = (const float*)d_in[2];
    const float* Wk    = (const float*)d_in[3];
    const float* Wv    = (const float*)d_in[4];
    const float* We    = (const float*)d_in[5];
    const float* Ohw   = (const float*)d_in[6];
    const float* Ohb   = (const float*)d_in[7];
    const float* Oew   = (const float*)d_in[8];
    const float* Oeb   = (const float*)d_in[9];
    const float* bn1hg = (const float*)d_in[10];
    const float* bn1hb = (const float*)d_in[11];
    const float* bn1eg = (const float*)d_in[12];
    const float* bn1eb = (const float*)d_in[13];
    const float* fhw1  = (const float*)d_in[14];
    const float* fhb1  = (const float*)d_in[15];
    const float* fhw2  = (const float*)d_in[16];
    const float* fhb2  = (const float*)d_in[17];
    const float* few1  = (const float*)d_in[18];
    const float* feb1  = (const float*)d_in[19];
    const float* few2  = (const float*)d_in[20];
    const float* feb2  = (const float*)d_in[21];
    const float* bn2hg = (const float*)d_in[22];
    const float* bn2hb = (const float*)d_in[23];
    const float* bn2eg = (const float*)d_in[24];
    const float* bn2eb = (const float*)d_in[25];
    const int*   src   = (const int*)d_in[26];
    const int*   dst   = (const int*)d_in[27];

    float* out  = (float*)d_out;
    float* outh = out;
    float* oute = out + (size_t)NN * D;

    float *pQ, *pK, *pV, *ppe, *pwV, *pz, *ph2, *pe2, *pstats, *pbnab;
    __nv_bfloat16* pimg;
    cudaGetSymbolAddress((void**)&pQ,    g_Q);
    cudaGetSymbolAddress((void**)&pK,    g_Kb);
    cudaGetSymbolAddress((void**)&pV,    g_V);
    cudaGetSymbolAddress((void**)&ppe,   g_pe);
    cudaGetSymbolAddress((void**)&pwV,   g_wV);
    cudaGetSymbolAddress((void**)&pz,    g_z);
    cudaGetSymbolAddress((void**)&ph2,   g_h2);
    cudaGetSymbolAddress((void**)&pe2,   g_e2);
    cudaGetSymbolAddress((void**)&pstats, g_stats);
    cudaGetSymbolAddress((void**)&pbnab,  g_bnab);
    cudaGetSymbolAddress((void**)&pimg,   g_wimg);

    const size_t oWe = 0, oWq = 32768, oWk = 65536, oWv = 98304;
    const size_t oOh = 131072, oOe = 163840;
    const size_t oF1h = 196608, oF1e = 262144, oF2h = 327680, oF2e = 393216;

    auto kA  = mm_k<0, 0, 0, 0, 0, 0, 0>;   // plain projection
    auto kAE = mm_k<0, 0, 0, 0, 0, 0, 1>;   // e projection + fused edge attention
    auto kBh = mm_k<0, 0, 1, 1, 1, 1, 0>;   // h O-proj: divz, +bias +res +stats
    auto kBe = mm_k<0, 0, 1, 1, 1, 0, 0>;   // e O-proj: +bias +res +stats

    const int SMEM   = 2 * 128 * 136 * 2;    // 69632
    const int SMEM_F = 2 * 128 * 264 * 2;    // 135168
    cudaFuncSetAttribute(kA,  cudaFuncAttributeMaxDynamicSharedMemorySize, SMEM);
    cudaFuncSetAttribute(kAE, cudaFuncAttributeMaxDynamicSharedMemorySize, SMEM);
    cudaFuncSetAttribute(kBh, cudaFuncAttributeMaxDynamicSharedMemorySize, SMEM);
    cudaFuncSetAttribute(kBe, cudaFuncAttributeMaxDynamicSharedMemorySize, SMEM);
    cudaFuncSetAttribute(ffn_k, cudaFuncAttributeMaxDynamicSharedMemorySize, SMEM_F);

    const int gN = (NN + 127) / 128;
    const int gE = (NE + 127) / 128;

    cudaMemsetAsync(pwV,    0, sizeof(float) * NN * D);
    cudaMemsetAsync(pz,     0, sizeof(float) * NN * 8);
    cudaMemsetAsync(pstats, 0, sizeof(float) * 4 * 2 * D);

    prep_w<<<64, 256>>>(We,  128, 128, pimg + oWe);
    prep_w<<<64, 256>>>(Wq,  128, 128, pimg + oWq);
    prep_w<<<64, 256>>>(Wk,  128, 128, pimg + oWk);
    prep_w<<<64, 256>>>(Wv,  128, 128, pimg + oWv);
    prep_w<<<64, 256>>>(Ohw, 128, 128, pimg + oOh);
    prep_w<<<64, 256>>>(Oew, 128, 128, pimg + oOe);
    prep_w<<<128, 256>>>(fhw1, 128, 256, pimg + oF1h);
    prep_w<<<128, 256>>>(few1, 128, 256, pimg + oF1e);
    prep_w<<<128, 256>>>(fhw2, 256, 128, pimg + oF2h);
    prep_w<<<128, 256>>>(few2, 256, 128, pimg + oF2e);

    // node projections
    kA<<<dim3(1, gN), 256, SMEM>>>(h_in, pimg + oWq, nullptr, nullptr, nullptr, nullptr, nullptr, nullptr, nullptr, nullptr, pQ, NN);
    kA<<<dim3(1, gN), 256, SMEM>>>(h_in, pimg + oWk, nullptr, nullptr, nullptr, nullptr, nullptr, nullptr, nullptr, nullptr, pK, NN);
    kA<<<dim3(1, gN), 256, SMEM>>>(h_in, pimg + oWv, nullptr, nullptr, nullptr, nullptr, nullptr, nullptr, nullptr, nullptr, pV, NN);

    // e projection + fused edge attention (writes score to ppe, scatters to wV/z)
    kAE<<<dim3(1, gE), 256, SMEM>>>(e_in, pimg + oWe, nullptr, nullptr, nullptr, nullptr, nullptr, nullptr, src, dst, ppe, NE);

    // O projections + residual + bn1 stats
    kBh<<<dim3(1, gN), 256, SMEM>>>(pwV, pimg + oOh, Ohb, h_in, nullptr, nullptr, pz, pstats + 0 * 2 * D, nullptr, nullptr, ph2, NN);
    kBe<<<dim3(1, gE), 256, SMEM>>>(ppe, pimg + oOe, Oeb, e_in, nullptr, nullptr, nullptr, pstats + 1 * 2 * D, nullptr, nullptr, pe2, NE);
    finalize_bn<<<1, D>>>(0, bn1hg, bn1hb, 1.f / NN);
    finalize_bn<<<1, D>>>(1, bn1eg, bn1eb, 1.f / NE);

    // fused FFNs
    ffn_k<<<gN, 512, SMEM_F>>>(ph2, pimg + oF1h, fhb1, pimg + oF2h, fhb2, pbnab + 0 * 2 * D, pstats + 2 * 2 * D, outh, NN);
    ffn_k<<<gE, 512, SMEM_F>>>(pe2, pimg + oF1e, feb1, pimg + oF2e, feb2, pbnab + 1 * 2 * D, pstats + 3 * 2 * D, oute, NE);

    finalize_bn<<<1, D>>>(2, bn2hg, bn2hb, 1.f / NN);
    finalize_bn<<<1, D>>>(3, bn2eg, bn2eb, 1.f / NE);

    out_norm<<<(int)(((size_t)(NN + NE) * D + 255) / 256), 256>>>(out);
}

// round 6
// speedup vs baseline: 3.3146x; 1.0803x over previous
#include <cuda_runtime.h>
#include <cuda_bf16.h>
#include <math.h>
#include <stdint.h>

#define NN 50000
#define NE 800000
#define D  128

// ---------------- scratch ----------------
static __device__ float g_Q  [NN * D];
static __device__ float g_Kb [NN * D];
static __device__ float g_V  [NN * D];
static __device__ float g_wV [NN * D];
static __device__ float g_z  [NN * 8];
static __device__ float g_h2 [NN * D];
static __device__ float g_pe [(size_t)NE * D];   // e_attn_out (score)
static __device__ float g_e2 [(size_t)NE * D];
static __device__ float g_stats[4 * 2 * D];
static __device__ float g_bnab [4 * 2 * D];
static __device__ __nv_bfloat16 g_wimg[458752];

// ---------------- weight prep (fragment-ordered, hi/lo packed per uint4) ----------------
__global__ void prep_w(const float* __restrict__ W, int K, int N, __nv_bfloat16* __restrict__ img)
{
    int idx = blockIdx.x * blockDim.x + threadIdx.x;
    if (idx >= K * N) return;
    int k = idx / N, n = idx - k * N;
    float w = __ldg(W + idx);
    __nv_bfloat16 hi = __float2bfloat16(w);
    __nv_bfloat16 lo = __float2bfloat16(w - __bfloat162float(hi));
    int kstep = k >> 4, kin = k & 15;
    int reg  = (kin >> 3) & 1;
    int tid4 = (kin >> 1) & 3;
    int p    = kin & 1;
    int gg   = n & 7;
    int ntile = n >> 3;
    int lane = gg * 4 + tid4;
    size_t idx4 = ((size_t)kstep * (N >> 3) + ntile) * 32 + lane;
    img[idx4 * 8 + reg * 2 + p]     = hi;
    img[idx4 * 8 + 4 + reg * 2 + p] = lo;
}

__device__ __forceinline__ void mma16816(float* c, const uint32_t* a, uint32_t b0, uint32_t b1)
{
    asm volatile(
        "mma.sync.aligned.m16n8k16.row.col.f32.bf16.bf16.f32 "
        "{%0,%1,%2,%3}, {%4,%5,%6,%7}, {%8,%9}, {%0,%1,%2,%3};"
        : "+f"(c[0]), "+f"(c[1]), "+f"(c[2]), "+f"(c[3])
        : "r"(a[0]), "r"(a[1]), "r"(a[2]), "r"(a[3]), "r"(b0), "r"(b1));
}

__device__ __forceinline__ void split_store(__nv_bfloat16* Ah, __nv_bfloat16* Al,
                                            int off, float4 v)
{
    __nv_bfloat162 h0 = __floats2bfloat162_rn(v.x, v.y);
    __nv_bfloat162 h1 = __floats2bfloat162_rn(v.z, v.w);
    __nv_bfloat162 l0 = __floats2bfloat162_rn(v.x - __bfloat162float(h0.x),
                                              v.y - __bfloat162float(h0.y));
    __nv_bfloat162 l1 = __floats2bfloat162_rn(v.z - __bfloat162float(h1.x),
                                              v.w - __bfloat162float(h1.y));
    *(__nv_bfloat162*)(Ah + off)     = h0;
    *(__nv_bfloat162*)(Ah + off + 2) = h1;
    *(__nv_bfloat162*)(Al + off)     = l0;
    *(__nv_bfloat162*)(Al + off + 2) = l1;
}

// load 8 A fragments (hi+lo for 2 m-tiles) from smem
template<int STRIDE>
__device__ __forceinline__ void load_afrag(const __nv_bfloat16* Ah, const __nv_bfloat16* Al,
                                           int r0, int kk, uint32_t ah[2][4], uint32_t al[2][4])
{
    #pragma unroll
    for (int mt = 0; mt < 2; mt++) {
        int r = r0 + mt * 16;
        ah[mt][0] = *(const uint32_t*)(Ah + (r    ) * STRIDE + kk);
        ah[mt][1] = *(const uint32_t*)(Ah + (r + 8) * STRIDE + kk);
        ah[mt][2] = *(const uint32_t*)(Ah + (r    ) * STRIDE + kk + 8);
        ah[mt][3] = *(const uint32_t*)(Ah + (r + 8) * STRIDE + kk + 8);
        al[mt][0] = *(const uint32_t*)(Al + (r    ) * STRIDE + kk);
        al[mt][1] = *(const uint32_t*)(Al + (r + 8) * STRIDE + kk);
        al[mt][2] = *(const uint32_t*)(Al + (r    ) * STRIDE + kk + 8);
        al[mt][3] = *(const uint32_t*)(Al + (r + 8) * STRIDE + kk + 8);
    }
}

// ---------------- generic 128x128 GEMM (+optional fused edge attention) ----------------
template<int BN_IN, int RELU, int BIAS, int RESM, int DO_STATS, int DIVZ, int EDGE>
__global__ void __launch_bounds__(256)
mm_k(const float* __restrict__ X, const __nv_bfloat16* __restrict__ Wimg,
     const float* __restrict__ bias, const float* __restrict__ res,
     const float* __restrict__ in_ab, const float* __restrict__ res_ab,
     const float* __restrict__ zdiv, float* __restrict__ stats,
     const int* __restrict__ src, const int* __restrict__ dst,
     float* __restrict__ C, int M)
{
    constexpr int SAP = 136;
    extern __shared__ __nv_bfloat16 sA[];
    __nv_bfloat16* Ah = sA;
    __nv_bfloat16* Al = sA + 128 * SAP;

    const int tid  = threadIdx.x;
    const int w    = tid >> 5, lane = tid & 31;
    const int wr   = w >> 1, wc = w & 1;
    const int g    = lane >> 2, tid4 = lane & 3;
    const int row0 = blockIdx.y * 128;

    const uint4* Bimg = (const uint4*)Wimg;

    float acc[2][8][4];
    #pragma unroll
    for (int mt = 0; mt < 2; mt++)
        #pragma unroll
        for (int nt = 0; nt < 8; nt++)
            #pragma unroll
            for (int i = 0; i < 4; i++) acc[mt][nt][i] = 0.f;

    #pragma unroll 4
    for (int i = tid; i < 4096; i += 256) {
        int r = i >> 5, c4 = i & 31, col = c4 * 4;
        float4 v = make_float4(0.f, 0.f, 0.f, 0.f);
        int gr = row0 + r;
        if (gr < M) {
            v = __ldg((const float4*)(X + (size_t)gr * 128) + c4);
            if (BN_IN) {
                v.x = fmaf(v.x, __ldg(in_ab + col + 0), __ldg(in_ab + 128 + col + 0));
                v.y = fmaf(v.y, __ldg(in_ab + col + 1), __ldg(in_ab + 128 + col + 1));
                v.z = fmaf(v.z, __ldg(in_ab + col + 2), __ldg(in_ab + 128 + col + 2));
                v.w = fmaf(v.w, __ldg(in_ab + col + 3), __ldg(in_ab + 128 + col + 3));
            }
            if (DIVZ) {
                float inv = 1.0f / (__ldg(zdiv + gr * 8 + (c4 >> 2)) + 1e-6f);
                v.x *= inv; v.y *= inv; v.z *= inv; v.w *= inv;
            }
        }
        split_store(Ah, Al, r * SAP + col, v);
    }
    __syncthreads();

    #pragma unroll
    for (int ks = 0; ks < 8; ks++) {
        uint4 b[8];
        #pragma unroll
        for (int nt = 0; nt < 8; nt++)
            b[nt] = __ldg(Bimg + ((size_t)ks * 16 + (wc * 8 + nt)) * 32 + lane);
        uint32_t ah[2][4], al[2][4];
        load_afrag<SAP>(Ah, Al, wr * 32 + g, ks * 16 + tid4 * 2, ah, al);
        #pragma unroll
        for (int nt = 0; nt < 8; nt++) {
            #pragma unroll
            for (int mt = 0; mt < 2; mt++) mma16816(acc[mt][nt], ah[mt], b[nt].x, b[nt].y);
            #pragma unroll
            for (int mt = 0; mt < 2; mt++) mma16816(acc[mt][nt], ah[mt], b[nt].z, b[nt].w);
            #pragma unroll
            for (int mt = 0; mt < 2; mt++) mma16816(acc[mt][nt], al[mt], b[nt].x, b[nt].y);
        }
    }
    __syncthreads();

    if (EDGE) {
        float* P = (float*)sA;
        #pragma unroll
        for (int mt = 0; mt < 2; mt++)
            #pragma unroll
            for (int half = 0; half < 2; half++) {
                int rl = wr * 32 + mt * 16 + g + half * 8;
                #pragma unroll
                for (int nt = 0; nt < 8; nt++) {
                    int col = wc * 64 + nt * 8 + tid4 * 2;
                    *(float2*)(P + rl * 132 + col) =
                        make_float2(acc[mt][nt][half * 2 + 0], acc[mt][nt][half * 2 + 1]);
                }
            }
        __syncthreads();
        for (int i = 0; i < 16; i++) {
            int rl = w * 16 + i;
            int er = row0 + rl;
            if (er >= M) break;
            int s = __ldg(src + er), d = __ldg(dst + er);
            float4 p = *(float4*)(P + rl * 132 + lane * 4);
            float4 q = __ldg((const float4*)(g_Q  + (size_t)d * D) + lane);
            float4 k = __ldg((const float4*)(g_Kb + (size_t)s * D) + lane);
            float4 sc;
            sc.x = k.x * q.x * 0.25f * p.x;
            sc.y = k.y * q.y * 0.25f * p.y;
            sc.z = k.z * q.z * 0.25f * p.z;
            sc.w = k.w * q.w * 0.25f * p.w;
            *((float4*)(C + (size_t)er * D) + lane) = sc;
            float part = sc.x + sc.y + sc.z + sc.w;
            part += __shfl_xor_sync(0xffffffffu, part, 1);
            part += __shfl_xor_sync(0xffffffffu, part, 2);
            part  = fminf(fmaxf(part, -5.f), 5.f);
            float sh = expf(part);
            float4 v = __ldg((const float4*)(g_V + (size_t)s * D) + lane);
            float* wv = g_wV + (size_t)d * D + lane * 4;
            asm volatile("red.global.add.v4.f32 [%0], {%1, %2, %3, %4};"
                         :: "l"(wv), "f"(v.x * sh), "f"(v.y * sh), "f"(v.z * sh), "f"(v.w * sh)
                         : "memory");
            if ((lane & 3) == 0) atomicAdd(g_z + (size_t)d * 8 + (lane >> 2), sh);
        }
        return;
    }

    float s1[16], s2[16];
    if (DO_STATS) {
        #pragma unroll
        for (int j = 0; j < 16; j++) { s1[j] = 0.f; s2[j] = 0.f; }
    }
    #pragma unroll
    for (int mt = 0; mt < 2; mt++)
        #pragma unroll
        for (int half = 0; half < 2; half++) {
            int gr = row0 + wr * 32 + mt * 16 + g + half * 8;
            if (gr >= M) continue;
            #pragma unroll
            for (int nt = 0; nt < 8; nt++) {
                int col = wc * 64 + nt * 8 + tid4 * 2;
                float o0 = acc[mt][nt][half * 2 + 0];
                float o1 = acc[mt][nt][half * 2 + 1];
                if (BIAS) { o0 += __ldg(bias + col); o1 += __ldg(bias + col + 1); }
                if (RESM) {
                    float2 rv = __ldg((const float2*)(res + (size_t)gr * D + col));
                    if (RESM == 1) { o0 += rv.x; o1 += rv.y; }
                    else {
                        o0 = fmaf(rv.x, __ldg(res_ab + col),     o0 + __ldg(res_ab + 128 + col));
                        o1 = fmaf(rv.y, __ldg(res_ab + col + 1), o1 + __ldg(res_ab + 128 + col + 1));
                    }
                }
                if (RELU) { o0 = fmaxf(o0, 0.f); o1 = fmaxf(o1, 0.f); }
                if (DO_STATS) {
                    s1[nt * 2 + 0] += o0; s2[nt * 2 + 0] = fmaf(o0, o0, s2[nt * 2 + 0]);
                    s1[nt * 2 + 1] += o1; s2[nt * 2 + 1] = fmaf(o1, o1, s2[nt * 2 + 1]);
                }
                *(float2*)(C + (size_t)gr * D + col) = make_float2(o0, o1);
            }
        }
    if (DO_STATS) {
        #pragma unroll
        for (int j = 0; j < 16; j++) {
            float a = s1[j], q = s2[j];
            a += __shfl_xor_sync(0xffffffffu, a, 4);  q += __shfl_xor_sync(0xffffffffu, q, 4);
            a += __shfl_xor_sync(0xffffffffu, a, 8);  q += __shfl_xor_sync(0xffffffffu, q, 8);
            a += __shfl_xor_sync(0xffffffffu, a, 16); q += __shfl_xor_sync(0xffffffffu, q, 16);
            if (g == 0) {
                int col = wc * 64 + (j >> 1) * 8 + tid4 * 2 + (j & 1);
                atomicAdd(stats + col, a);
                atomicAdd(stats + 128 + col, q);
            }
        }
    }
}

// ---------------- fused QKV: stage h tile once, 3 GEMMs ----------------
__global__ void __launch_bounds__(256)
qkv_k(const float* __restrict__ X,
      const __nv_bfloat16* __restrict__ Wq, const __nv_bfloat16* __restrict__ Wk,
      const __nv_bfloat16* __restrict__ Wv,
      float* __restrict__ Cq, float* __restrict__ Ck, float* __restrict__ Cv, int M)
{
    constexpr int SAP = 136;
    extern __shared__ __nv_bfloat16 sA[];
    __nv_bfloat16* Ah = sA;
    __nv_bfloat16* Al = sA + 128 * SAP;

    const int tid  = threadIdx.x;
    const int w    = tid >> 5, lane = tid & 31;
    const int wr   = w >> 1, wc = w & 1;
    const int g    = lane >> 2, tid4 = lane & 3;
    const int row0 = blockIdx.y * 128;

    #pragma unroll 4
    for (int i = tid; i < 4096; i += 256) {
        int r = i >> 5, c4 = i & 31, col = c4 * 4;
        float4 v = make_float4(0.f, 0.f, 0.f, 0.f);
        int gr = row0 + r;
        if (gr < M) v = __ldg((const float4*)(X + (size_t)gr * 128) + c4);
        split_store(Ah, Al, r * SAP + col, v);
    }
    __syncthreads();

    const __nv_bfloat16* Ws[3] = {Wq, Wk, Wv};
    float* Cs[3] = {Cq, Ck, Cv};
    #pragma unroll 1
    for (int wsel = 0; wsel < 3; wsel++) {
        const uint4* Bimg = (const uint4*)Ws[wsel];
        float* C = Cs[wsel];
        float acc[2][8][4];
        #pragma unroll
        for (int mt = 0; mt < 2; mt++)
            #pragma unroll
            for (int nt = 0; nt < 8; nt++)
                #pragma unroll
                for (int i = 0; i < 4; i++) acc[mt][nt][i] = 0.f;
        #pragma unroll
        for (int ks = 0; ks < 8; ks++) {
            uint4 b[8];
            #pragma unroll
            for (int nt = 0; nt < 8; nt++)
                b[nt] = __ldg(Bimg + ((size_t)ks * 16 + (wc * 8 + nt)) * 32 + lane);
            uint32_t ah[2][4], al[2][4];
            load_afrag<SAP>(Ah, Al, wr * 32 + g, ks * 16 + tid4 * 2, ah, al);
            #pragma unroll
            for (int nt = 0; nt < 8; nt++) {
                #pragma unroll
                for (int mt = 0; mt < 2; mt++) mma16816(acc[mt][nt], ah[mt], b[nt].x, b[nt].y);
                #pragma unroll
                for (int mt = 0; mt < 2; mt++) mma16816(acc[mt][nt], ah[mt], b[nt].z, b[nt].w);
                #pragma unroll
                for (int mt = 0; mt < 2; mt++) mma16816(acc[mt][nt], al[mt], b[nt].x, b[nt].y);
            }
        }
        #pragma unroll
        for (int mt = 0; mt < 2; mt++)
            #pragma unroll
            for (int half = 0; half < 2; half++) {
                int gr = row0 + wr * 32 + mt * 16 + g + half * 8;
                if (gr >= M) continue;
                #pragma unroll
                for (int nt = 0; nt < 8; nt++) {
                    int col = wc * 64 + nt * 8 + tid4 * 2;
                    *(float2*)(C + (size_t)gr * D + col) =
                        make_float2(acc[mt][nt][half * 2 + 0], acc[mt][nt][half * 2 + 1]);
                }
            }
    }
}

// ---------------- fused FFN, 64-row tiles, 256 threads ----------------
__global__ void __launch_bounds__(256)
ffn_k(const float* __restrict__ X, const __nv_bfloat16* __restrict__ W1img,
      const float* __restrict__ b1, const __nv_bfloat16* __restrict__ W2img,
      const float* __restrict__ b2, const float* __restrict__ bnab,
      float* __restrict__ stats, float* __restrict__ C, int M)
{
    constexpr int SAP = 136, MP = 264;
    extern __shared__ __nv_bfloat16 sm[];
    __nv_bfloat16* Ah = sm;
    __nv_bfloat16* Al = sm + 64 * SAP;
    __nv_bfloat16* Mh = sm;
    __nv_bfloat16* Ml = sm + 64 * MP;

    const int tid  = threadIdx.x;
    const int w    = tid >> 5, lane = tid & 31;
    const int wr   = w >> 2, wc = w & 3;           // 2x4 warp grid
    const int g    = lane >> 2, tid4 = lane & 3;
    const int row0 = blockIdx.x * 64;

    const uint4* B1 = (const uint4*)W1img;
    const uint4* B2 = (const uint4*)W2img;

    // ---- stage A = BN(X), 64 rows ----
    #pragma unroll 2
    for (int i = tid; i < 2048; i += 256) {
        int r = i >> 5, c4 = i & 31, col = c4 * 4;
        float4 v = make_float4(0.f, 0.f, 0.f, 0.f);
        int gr = row0 + r;
        if (gr < M) {
            v = __ldg((const float4*)(X + (size_t)gr * 128) + c4);
            v.x = fmaf(v.x, __ldg(bnab + col + 0), __ldg(bnab + 128 + col + 0));
            v.y = fmaf(v.y, __ldg(bnab + col + 1), __ldg(bnab + 128 + col + 1));
            v.z = fmaf(v.z, __ldg(bnab + col + 2), __ldg(bnab + 128 + col + 2));
            v.w = fmaf(v.w, __ldg(bnab + col + 3), __ldg(bnab + 128 + col + 3));
        }
        split_store(Ah, Al, r * SAP + col, v);
    }
    __syncthreads();

    // ---- FFN1: 64x256, warp tile 32x64 ----
    float acc1[2][8][4];
    #pragma unroll
    for (int mt = 0; mt < 2; mt++)
        #pragma unroll
        for (int nt = 0; nt < 8; nt++)
            #pragma unroll
            for (int i = 0; i < 4; i++) acc1[mt][nt][i] = 0.f;

    #pragma unroll
    for (int ks = 0; ks < 8; ks++) {
        uint32_t ah[2][4], al[2][4];
        load_afrag<SAP>(Ah, Al, wr * 32 + g, ks * 16 + tid4 * 2, ah, al);
        #pragma unroll
        for (int nt = 0; nt < 8; nt++) {
            uint4 b = __ldg(B1 + ((size_t)ks * 32 + (wc * 8 + nt)) * 32 + lane);
            #pragma unroll
            for (int mt = 0; mt < 2; mt++) mma16816(acc1[mt][nt], ah[mt], b.x, b.y);
            #pragma unroll
            for (int mt = 0; mt < 2; mt++) mma16816(acc1[mt][nt], ah[mt], b.z, b.w);
            #pragma unroll
            for (int mt = 0; mt < 2; mt++) mma16816(acc1[mt][nt], al[mt], b.x, b.y);
        }
    }
    __syncthreads();

    // ---- mid = relu(acc1 + b1) -> smem ----
    #pragma unroll
    for (int mt = 0; mt < 2; mt++)
        #pragma unroll
        for (int half = 0; half < 2; half++) {
            int rl = wr * 32 + mt * 16 + g + half * 8;
            #pragma unroll
            for (int nt = 0; nt < 8; nt++) {
                int col = wc * 64 + nt * 8 + tid4 * 2;
                float o0 = fmaxf(acc1[mt][nt][half * 2 + 0] + __ldg(b1 + col), 0.f);
                float o1 = fmaxf(acc1[mt][nt][half * 2 + 1] + __ldg(b1 + col + 1), 0.f);
                __nv_bfloat162 h = __floats2bfloat162_rn(o0, o1);
                __nv_bfloat162 l = __floats2bfloat162_rn(o0 - __bfloat162float(h.x),
                                                         o1 - __bfloat162float(h.y));
                *(__nv_bfloat162*)(Mh + rl * MP + col) = h;
                *(__nv_bfloat162*)(Ml + rl * MP + col) = l;
            }
        }
    __syncthreads();

    // ---- FFN2: 64x128, K=256, warp tile 32x32 ----
    float acc2[2][4][4];
    #pragma unroll
    for (int mt = 0; mt < 2; mt++)
        #pragma unroll
        for (int nt = 0; nt < 4; nt++)
            #pragma unroll
            for (int i = 0; i < 4; i++) acc2[mt][nt][i] = 0.f;

    #pragma unroll
    for (int ks = 0; ks < 16; ks++) {
        uint32_t ah[2][4], al[2][4];
        load_afrag<MP>(Mh, Ml, wr * 32 + g, ks * 16 + tid4 * 2, ah, al);
        #pragma unroll
        for (int nt = 0; nt < 4; nt++) {
            uint4 b = __ldg(B2 + ((size_t)ks * 16 + (wc * 4 + nt)) * 32 + lane);
            #pragma unroll
            for (int mt = 0; mt < 2; mt++) mma16816(acc2[mt][nt], ah[mt], b.x, b.y);
            #pragma unroll
            for (int mt = 0; mt < 2; mt++) mma16816(acc2[mt][nt], ah[mt], b.z, b.w);
            #pragma unroll
            for (int mt = 0; mt < 2; mt++) mma16816(acc2[mt][nt], al[mt], b.x, b.y);
        }
    }

    // ---- epilogue ----
    float s1[8], s2[8];
    #pragma unroll
    for (int j = 0; j < 8; j++) { s1[j] = 0.f; s2[j] = 0.f; }
    #pragma unroll
    for (int mt = 0; mt < 2; mt++)
        #pragma unroll
        for (int half = 0; half < 2; half++) {
            int gr = row0 + wr * 32 + mt * 16 + g + half * 8;
            if (gr >= M) continue;
            #pragma unroll
            for (int nt = 0; nt < 4; nt++) {
                int col = wc * 32 + nt * 8 + tid4 * 2;
                float o0 = acc2[mt][nt][half * 2 + 0] + __ldg(b2 + col);
                float o1 = acc2[mt][nt][half * 2 + 1] + __ldg(b2 + col + 1);
                float2 rv = __ldg((const float2*)(X + (size_t)gr * 128 + col));
                o0 = fmaf(rv.x, __ldg(bnab + col),     o0 + __ldg(bnab + 128 + col));
                o1 = fmaf(rv.y, __ldg(bnab + col + 1), o1 + __ldg(bnab + 128 + col + 1));
                s1[nt * 2 + 0] += o0; s2[nt * 2 + 0] = fmaf(o0, o0, s2[nt * 2 + 0]);
                s1[nt * 2 + 1] += o1; s2[nt * 2 + 1] = fmaf(o1, o1, s2[nt * 2 + 1]);
                *(float2*)(C + (size_t)gr * 128 + col) = make_float2(o0, o1);
            }
        }
    #pragma unroll
    for (int j = 0; j < 8; j++) {
        float a = s1[j], q = s2[j];
        a += __shfl_xor_sync(0xffffffffu, a, 4);  q += __shfl_xor_sync(0xffffffffu, q, 4);
        a += __shfl_xor_sync(0xffffffffu, a, 8);  q += __shfl_xor_sync(0xffffffffu, q, 8);
        a += __shfl_xor_sync(0xffffffffu, a, 16); q += __shfl_xor_sync(0xffffffffu, q, 16);
        if (g == 0) {
            int col = wc * 32 + (j >> 1) * 8 + tid4 * 2 + (j & 1);
            atomicAdd(stats + col, a);
            atomicAdd(stats + 128 + col, q);
        }
    }
}

__global__ void finalize_bn(int bn, const float* __restrict__ g, const float* __restrict__ b, float minv)
{
    int c = threadIdx.x;
    float mean = g_stats[bn * 2 * D + c] * minv;
    float var  = g_stats[bn * 2 * D + D + c] * minv - mean * mean;
    float rstd = rsqrtf(var + 1e-5f);
    float scv  = g[c] * rstd;
    g_bnab[bn * 2 * D + c]     = scv;
    g_bnab[bn * 2 * D + D + c] = b[c] - mean * scv;
}

__global__ void out_norm(float* __restrict__ out)
{
    size_t i = (size_t)blockIdx.x * blockDim.x + threadIdx.x;
    if (i < (size_t)(NN + NE) * D) {
        int c  = (int)(i & 127);
        int bn = (i < (size_t)NN * D) ? 2 : 3;
        out[i] = fmaf(out[i], g_bnab[bn * 2 * D + c], g_bnab[bn * 2 * D + D + c]);
    }
}

// ---------------- host ----------------
extern "C" void kernel_launch(void* const* d_in, const int* in_sizes, int n_in,
                              void* d_out, int out_size)
{
    (void)in_sizes; (void)n_in; (void)out_size;
    const float* h_in  = (const float*)d_in[0];
    const float* e_in  = (const float*)d_in[1];
    const float* Wq    = (const float*)d_in[2];
    const float* Wk    = (const float*)d_in[3];
    const float* Wv    = (const float*)d_in[4];
    const float* We    = (const float*)d_in[5];
    const float* Ohw   = (const float*)d_in[6];
    const float* Ohb   = (const float*)d_in[7];
    const float* Oew   = (const float*)d_in[8];
    const float* Oeb   = (const float*)d_in[9];
    const float* bn1hg = (const float*)d_in[10];
    const float* bn1hb = (const float*)d_in[11];
    const float* bn1eg = (const float*)d_in[12];
    const float* bn1eb = (const float*)d_in[13];
    const float* fhw1  = (const float*)d_in[14];
    const float* fhb1  = (const float*)d_in[15];
    const float* fhw2  = (const float*)d_in[16];
    const float* fhb2  = (const float*)d_in[17];
    const float* few1  = (const float*)d_in[18];
    const float* feb1  = (const float*)d_in[19];
    const float* few2  = (const float*)d_in[20];
    const float* feb2  = (const float*)d_in[21];
    const float* bn2hg = (const float*)d_in[22];
    const float* bn2hb = (const float*)d_in[23];
    const float* bn2eg = (const float*)d_in[24];
    const float* bn2eb = (const float*)d_in[25];
    const int*   src   = (const int*)d_in[26];
    const int*   dst   = (const int*)d_in[27];

    float* out  = (float*)d_out;
    float* outh = out;
    float* oute = out + (size_t)NN * D;

    float *pQ, *pK, *pV, *ppe, *pwV, *pz, *ph2, *pe2, *pstats, *pbnab;
    __nv_bfloat16* pimg;
    cudaGetSymbolAddress((void**)&pQ,    g_Q);
    cudaGetSymbolAddress((void**)&pK,    g_Kb);
    cudaGetSymbolAddress((void**)&pV,    g_V);
    cudaGetSymbolAddress((void**)&ppe,   g_pe);
    cudaGetSymbolAddress((void**)&pwV,   g_wV);
    cudaGetSymbolAddress((void**)&pz,    g_z);
    cudaGetSymbolAddress((void**)&ph2,   g_h2);
    cudaGetSymbolAddress((void**)&pe2,   g_e2);
    cudaGetSymbolAddress((void**)&pstats, g_stats);
    cudaGetSymbolAddress((void**)&pbnab,  g_bnab);
    cudaGetSymbolAddress((void**)&pimg,   g_wimg);

    const size_t oWe = 0, oWq = 32768, oWk = 65536, oWv = 98304;
    const size_t oOh = 131072, oOe = 163840;
    const size_t oF1h = 196608, oF1e = 262144, oF2h = 327680, oF2e = 393216;

    auto kAE = mm_k<0, 0, 0, 0, 0, 0, 1>;   // e projection + fused edge attention
    auto kBh = mm_k<0, 0, 1, 1, 1, 1, 0>;   // h O-proj: divz, +bias +res +stats
    auto kBe = mm_k<0, 0, 1, 1, 1, 0, 0>;   // e O-proj: +bias +res +stats

    const int SMEM   = 2 * 128 * 136 * 2;    // 69632
    const int SMEM_F = 2 * 64 * 264 * 2;     // 67584
    cudaFuncSetAttribute(kAE,   cudaFuncAttributeMaxDynamicSharedMemorySize, SMEM);
    cudaFuncSetAttribute(kBh,   cudaFuncAttributeMaxDynamicSharedMemorySize, SMEM);
    cudaFuncSetAttribute(kBe,   cudaFuncAttributeMaxDynamicSharedMemorySize, SMEM);
    cudaFuncSetAttribute(qkv_k, cudaFuncAttributeMaxDynamicSharedMemorySize, SMEM);
    cudaFuncSetAttribute(ffn_k, cudaFuncAttributeMaxDynamicSharedMemorySize, SMEM_F);

    const int gN  = (NN + 127) / 128;
    const int gE  = (NE + 127) / 128;
    const int gN64 = (NN + 63) / 64;
    const int gE64 = (NE + 63) / 64;

    cudaMemsetAsync(pwV,    0, sizeof(float) * NN * D);
    cudaMemsetAsync(pz,     0, sizeof(float) * NN * 8);
    cudaMemsetAsync(pstats, 0, sizeof(float) * 4 * 2 * D);

    prep_w<<<64, 256>>>(We,  128, 128, pimg + oWe);
    prep_w<<<64, 256>>>(Wq,  128, 128, pimg + oWq);
    prep_w<<<64, 256>>>(Wk,  128, 128, pimg + oWk);
    prep_w<<<64, 256>>>(Wv,  128, 128, pimg + oWv);
    prep_w<<<64, 256>>>(Ohw, 128, 128, pimg + oOh);
    prep_w<<<64, 256>>>(Oew, 128, 128, pimg + oOe);
    prep_w<<<128, 256>>>(fhw1, 128, 256, pimg + oF1h);
    prep_w<<<128, 256>>>(few1, 128, 256, pimg + oF1e);
    prep_w<<<128, 256>>>(fhw2, 256, 128, pimg + oF2h);
    prep_w<<<128, 256>>>(few2, 256, 128, pimg + oF2e);

    // fused Q/K/V projection
    qkv_k<<<dim3(1, gN), 256, SMEM>>>(h_in, pimg + oWq, pimg + oWk, pimg + oWv, pQ, pK, pV, NN);

    // e projection + fused edge attention
    kAE<<<dim3(1, gE), 256, SMEM>>>(e_in, pimg + oWe, nullptr, nullptr, nullptr, nullptr, nullptr, nullptr, src, dst, ppe, NE);

    // O projections + residual + bn1 stats
    kBh<<<dim3(1, gN), 256, SMEM>>>(pwV, pimg + oOh, Ohb, h_in, nullptr, nullptr, pz, pstats + 0 * 2 * D, nullptr, nullptr, ph2, NN);
    kBe<<<dim3(1, gE), 256, SMEM>>>(ppe, pimg + oOe, Oeb, e_in, nullptr, nullptr, nullptr, pstats + 1 * 2 * D, nullptr, nullptr, pe2, NE);
    finalize_bn<<<1, D>>>(0, bn1hg, bn1hb, 1.f / NN);
    finalize_bn<<<1, D>>>(1, bn1eg, bn1eb, 1.f / NE);

    // fused FFNs (64-row tiles)
    ffn_k<<<gN64, 256, SMEM_F>>>(ph2, pimg + oF1h, fhb1, pimg + oF2h, fhb2, pbnab + 0 * 2 * D, pstats + 2 * 2 * D, outh, NN);
    ffn_k<<<gE64, 256, SMEM_F>>>(pe2, pimg + oF1e, feb1, pimg + oF2e, feb2, pbnab + 1 * 2 * D, pstats + 3 * 2 * D, oute, NE);

    finalize_bn<<<1, D>>>(2, bn2hg, bn2hb, 1.f / NN);
    finalize_bn<<<1, D>>>(3, bn2eg, bn2eb, 1.f / NE);

    out_norm<<<(int)(((size_t)(NN + NE) * D + 255) / 256), 256>>>(out);
}

// round 7
// speedup vs baseline: 4.0760x; 1.2297x over previous
#include <cuda_runtime.h>
#include <cuda_bf16.h>
#include <math.h>
#include <stdint.h>

#define NN 50000
#define NE 800000
#define D  128

// ---------------- scratch ----------------
static __device__ float g_Q  [NN * D];
static __device__ float g_Kb [NN * D];
static __device__ float g_V  [NN * D];
static __device__ float g_wV [NN * D];
static __device__ float g_z  [NN * 8];
static __device__ float g_h2 [NN * D];
static __device__ float g_e2 [(size_t)NE * D];
static __device__ float g_stats[4 * 2 * D];
static __device__ float g_bnab [4 * 2 * D];
static __device__ __nv_bfloat16 g_wimg[458752];

// ---------------- weight prep (fragment-ordered, hi/lo packed per uint4) ----------------
__global__ void prep_w(const float* __restrict__ W, int K, int N, __nv_bfloat16* __restrict__ img)
{
    int idx = blockIdx.x * blockDim.x + threadIdx.x;
    if (idx >= K * N) return;
    int k = idx / N, n = idx - k * N;
    float w = __ldg(W + idx);
    __nv_bfloat16 hi = __float2bfloat16(w);
    __nv_bfloat16 lo = __float2bfloat16(w - __bfloat162float(hi));
    int kstep = k >> 4, kin = k & 15;
    int reg  = (kin >> 3) & 1;
    int tid4 = (kin >> 1) & 3;
    int p    = kin & 1;
    int gg   = n & 7;
    int ntile = n >> 3;
    int lane = gg * 4 + tid4;
    size_t idx4 = ((size_t)kstep * (N >> 3) + ntile) * 32 + lane;
    img[idx4 * 8 + reg * 2 + p]     = hi;
    img[idx4 * 8 + 4 + reg * 2 + p] = lo;
}

__device__ __forceinline__ void mma16816(float* c, const uint32_t* a, uint32_t b0, uint32_t b1)
{
    asm volatile(
        "mma.sync.aligned.m16n8k16.row.col.f32.bf16.bf16.f32 "
        "{%0,%1,%2,%3}, {%4,%5,%6,%7}, {%8,%9}, {%0,%1,%2,%3};"
        : "+f"(c[0]), "+f"(c[1]), "+f"(c[2]), "+f"(c[3])
        : "r"(a[0]), "r"(a[1]), "r"(a[2]), "r"(a[3]), "r"(b0), "r"(b1));
}

__device__ __forceinline__ void split_store(__nv_bfloat16* Ah, __nv_bfloat16* Al,
                                            int off, float4 v)
{
    __nv_bfloat162 h0 = __floats2bfloat162_rn(v.x, v.y);
    __nv_bfloat162 h1 = __floats2bfloat162_rn(v.z, v.w);
    __nv_bfloat162 l0 = __floats2bfloat162_rn(v.x - __bfloat162float(h0.x),
                                              v.y - __bfloat162float(h0.y));
    __nv_bfloat162 l1 = __floats2bfloat162_rn(v.z - __bfloat162float(h1.x),
                                              v.w - __bfloat162float(h1.y));
    *(__nv_bfloat162*)(Ah + off)     = h0;
    *(__nv_bfloat162*)(Ah + off + 2) = h1;
    *(__nv_bfloat162*)(Al + off)     = l0;
    *(__nv_bfloat162*)(Al + off + 2) = l1;
}

template<int STRIDE>
__device__ __forceinline__ void load_afrag(const __nv_bfloat16* Ah, const __nv_bfloat16* Al,
                                           int r0, int kk, uint32_t ah[2][4], uint32_t al[2][4])
{
    #pragma unroll
    for (int mt = 0; mt < 2; mt++) {
        int r = r0 + mt * 16;
        ah[mt][0] = *(const uint32_t*)(Ah + (r    ) * STRIDE + kk);
        ah[mt][1] = *(const uint32_t*)(Ah + (r + 8) * STRIDE + kk);
        ah[mt][2] = *(const uint32_t*)(Ah + (r    ) * STRIDE + kk + 8);
        ah[mt][3] = *(const uint32_t*)(Ah + (r + 8) * STRIDE + kk + 8);
        al[mt][0] = *(const uint32_t*)(Al + (r    ) * STRIDE + kk);
        al[mt][1] = *(const uint32_t*)(Al + (r + 8) * STRIDE + kk);
        al[mt][2] = *(const uint32_t*)(Al + (r    ) * STRIDE + kk + 8);
        al[mt][3] = *(const uint32_t*)(Al + (r + 8) * STRIDE + kk + 8);
    }
}

// ---------------- h-side O-proj GEMM ----------------
template<int BIAS, int RESM, int DO_STATS, int DIVZ>
__global__ void __launch_bounds__(256)
mm_k(const float* __restrict__ X, const __nv_bfloat16* __restrict__ Wimg,
     const float* __restrict__ bias, const float* __restrict__ res,
     const float* __restrict__ res_ab,
     const float* __restrict__ zdiv, float* __restrict__ stats,
     float* __restrict__ C, int M)
{
    constexpr int SAP = 136;
    extern __shared__ __nv_bfloat16 sA[];
    __nv_bfloat16* Ah = sA;
    __nv_bfloat16* Al = sA + 128 * SAP;

    const int tid  = threadIdx.x;
    const int w    = tid >> 5, lane = tid & 31;
    const int wr   = w >> 1, wc = w & 1;
    const int g    = lane >> 2, tid4 = lane & 3;
    const int row0 = blockIdx.y * 128;

    const uint4* Bimg = (const uint4*)Wimg;

    float acc[2][8][4];
    #pragma unroll
    for (int mt = 0; mt < 2; mt++)
        #pragma unroll
        for (int nt = 0; nt < 8; nt++)
            #pragma unroll
            for (int i = 0; i < 4; i++) acc[mt][nt][i] = 0.f;

    #pragma unroll 4
    for (int i = tid; i < 4096; i += 256) {
        int r = i >> 5, c4 = i & 31, col = c4 * 4;
        float4 v = make_float4(0.f, 0.f, 0.f, 0.f);
        int gr = row0 + r;
        if (gr < M) {
            v = __ldg((const float4*)(X + (size_t)gr * 128) + c4);
            if (DIVZ) {
                float inv = 1.0f / (__ldg(zdiv + gr * 8 + (c4 >> 2)) + 1e-6f);
                v.x *= inv; v.y *= inv; v.z *= inv; v.w *= inv;
            }
        }
        split_store(Ah, Al, r * SAP + col, v);
    }
    __syncthreads();

    #pragma unroll
    for (int ks = 0; ks < 8; ks++) {
        uint4 b[8];
        #pragma unroll
        for (int nt = 0; nt < 8; nt++)
            b[nt] = __ldg(Bimg + ((size_t)ks * 16 + (wc * 8 + nt)) * 32 + lane);
        uint32_t ah[2][4], al[2][4];
        load_afrag<SAP>(Ah, Al, wr * 32 + g, ks * 16 + tid4 * 2, ah, al);
        #pragma unroll
        for (int nt = 0; nt < 8; nt++) {
            #pragma unroll
            for (int mt = 0; mt < 2; mt++) mma16816(acc[mt][nt], ah[mt], b[nt].x, b[nt].y);
            #pragma unroll
            for (int mt = 0; mt < 2; mt++) mma16816(acc[mt][nt], ah[mt], b[nt].z, b[nt].w);
            #pragma unroll
            for (int mt = 0; mt < 2; mt++) mma16816(acc[mt][nt], al[mt], b[nt].x, b[nt].y);
        }
    }

    float s1[16], s2[16];
    if (DO_STATS) {
        #pragma unroll
        for (int j = 0; j < 16; j++) { s1[j] = 0.f; s2[j] = 0.f; }
    }
    #pragma unroll
    for (int mt = 0; mt < 2; mt++)
        #pragma unroll
        for (int half = 0; half < 2; half++) {
            int gr = row0 + wr * 32 + mt * 16 + g + half * 8;
            if (gr >= M) continue;
            #pragma unroll
            for (int nt = 0; nt < 8; nt++) {
                int col = wc * 64 + nt * 8 + tid4 * 2;
                float o0 = acc[mt][nt][half * 2 + 0];
                float o1 = acc[mt][nt][half * 2 + 1];
                if (BIAS) { o0 += __ldg(bias + col); o1 += __ldg(bias + col + 1); }
                if (RESM) {
                    float2 rv = __ldg((const float2*)(res + (size_t)gr * D + col));
                    o0 += rv.x; o1 += rv.y;
                }
                if (DO_STATS) {
                    s1[nt * 2 + 0] += o0; s2[nt * 2 + 0] = fmaf(o0, o0, s2[nt * 2 + 0]);
                    s1[nt * 2 + 1] += o1; s2[nt * 2 + 1] = fmaf(o1, o1, s2[nt * 2 + 1]);
                }
                *(float2*)(C + (size_t)gr * D + col) = make_float2(o0, o1);
            }
        }
    if (DO_STATS) {
        #pragma unroll
        for (int j = 0; j < 16; j++) {
            float a = s1[j], q = s2[j];
            a += __shfl_xor_sync(0xffffffffu, a, 4);  q += __shfl_xor_sync(0xffffffffu, q, 4);
            a += __shfl_xor_sync(0xffffffffu, a, 8);  q += __shfl_xor_sync(0xffffffffu, q, 8);
            a += __shfl_xor_sync(0xffffffffu, a, 16); q += __shfl_xor_sync(0xffffffffu, q, 16);
            if (g == 0) {
                int col = wc * 64 + (j >> 1) * 8 + tid4 * 2 + (j & 1);
                atomicAdd(stats + col, a);
                atomicAdd(stats + 128 + col, q);
            }
        }
    }
}

// ---------------- fused QKV ----------------
__global__ void __launch_bounds__(256)
qkv_k(const float* __restrict__ X,
      const __nv_bfloat16* __restrict__ Wq, const __nv_bfloat16* __restrict__ Wk,
      const __nv_bfloat16* __restrict__ Wv,
      float* __restrict__ Cq, float* __restrict__ Ck, float* __restrict__ Cv, int M)
{
    constexpr int SAP = 136;
    extern __shared__ __nv_bfloat16 sA[];
    __nv_bfloat16* Ah = sA;
    __nv_bfloat16* Al = sA + 128 * SAP;

    const int tid  = threadIdx.x;
    const int w    = tid >> 5, lane = tid & 31;
    const int wr   = w >> 1, wc = w & 1;
    const int g    = lane >> 2, tid4 = lane & 3;
    const int row0 = blockIdx.y * 128;

    #pragma unroll 4
    for (int i = tid; i < 4096; i += 256) {
        int r = i >> 5, c4 = i & 31, col = c4 * 4;
        float4 v = make_float4(0.f, 0.f, 0.f, 0.f);
        int gr = row0 + r;
        if (gr < M) v = __ldg((const float4*)(X + (size_t)gr * 128) + c4);
        split_store(Ah, Al, r * SAP + col, v);
    }
    __syncthreads();

    const __nv_bfloat16* Ws[3] = {Wq, Wk, Wv};
    float* Cs[3] = {Cq, Ck, Cv};
    #pragma unroll 1
    for (int wsel = 0; wsel < 3; wsel++) {
        const uint4* Bimg = (const uint4*)Ws[wsel];
        float* C = Cs[wsel];
        float acc[2][8][4];
        #pragma unroll
        for (int mt = 0; mt < 2; mt++)
            #pragma unroll
            for (int nt = 0; nt < 8; nt++)
                #pragma unroll
                for (int i = 0; i < 4; i++) acc[mt][nt][i] = 0.f;
        #pragma unroll
        for (int ks = 0; ks < 8; ks++) {
            uint4 b[8];
            #pragma unroll
            for (int nt = 0; nt < 8; nt++)
                b[nt] = __ldg(Bimg + ((size_t)ks * 16 + (wc * 8 + nt)) * 32 + lane);
            uint32_t ah[2][4], al[2][4];
            load_afrag<SAP>(Ah, Al, wr * 32 + g, ks * 16 + tid4 * 2, ah, al);
            #pragma unroll
            for (int nt = 0; nt < 8; nt++) {
                #pragma unroll
                for (int mt = 0; mt < 2; mt++) mma16816(acc[mt][nt], ah[mt], b[nt].x, b[nt].y);
                #pragma unroll
                for (int mt = 0; mt < 2; mt++) mma16816(acc[mt][nt], ah[mt], b[nt].z, b[nt].w);
                #pragma unroll
                for (int mt = 0; mt < 2; mt++) mma16816(acc[mt][nt], al[mt], b[nt].x, b[nt].y);
            }
        }
        #pragma unroll
        for (int mt = 0; mt < 2; mt++)
            #pragma unroll
            for (int half = 0; half < 2; half++) {
                int gr = row0 + wr * 32 + mt * 16 + g + half * 8;
                if (gr >= M) continue;
                #pragma unroll
                for (int nt = 0; nt < 8; nt++) {
                    int col = wc * 64 + nt * 8 + tid4 * 2;
                    *(float2*)(C + (size_t)gr * D + col) =
                        make_float2(acc[mt][nt][half * 2 + 0], acc[mt][nt][half * 2 + 1]);
                }
            }
    }
}

// ---------------- fused edge pipeline ----------------
__global__ void __launch_bounds__(256)
epj_k(const float* __restrict__ X, const __nv_bfloat16* __restrict__ W1img,
      const __nv_bfloat16* __restrict__ W2img, const float* __restrict__ bias,
      const int* __restrict__ src, const int* __restrict__ dst,
      float* __restrict__ stats, float* __restrict__ C, int M)
{
    constexpr int SAP = 136;
    extern __shared__ __nv_bfloat16 sm[];
    __nv_bfloat16* Ah = sm;
    __nv_bfloat16* Al = sm + 64 * SAP;
    __nv_bfloat16* Sh = sm + 2 * 64 * SAP;
    __nv_bfloat16* Sl = sm + 3 * 64 * SAP;

    const int tid  = threadIdx.x;
    const int w    = tid >> 5, lane = tid & 31;
    const int wr   = w >> 2, wc = w & 3;
    const int g    = lane >> 2, tid4 = lane & 3;
    const int row0 = blockIdx.x * 64;

    const uint4* B1 = (const uint4*)W1img;
    const uint4* B2 = (const uint4*)W2img;

    #pragma unroll 2
    for (int i = tid; i < 2048; i += 256) {
        int r = i >> 5, c4 = i & 31, col = c4 * 4;
        float4 v = make_float4(0.f, 0.f, 0.f, 0.f);
        int gr = row0 + r;
        if (gr < M) v = __ldg((const float4*)(X + (size_t)gr * 128) + c4);
        split_store(Ah, Al, r * SAP + col, v);
    }
    __syncthreads();

    float acc1[2][4][4];
    #pragma unroll
    for (int mt = 0; mt < 2; mt++)
        #pragma unroll
        for (int nt = 0; nt < 4; nt++)
            #pragma unroll
            for (int i = 0; i < 4; i++) acc1[mt][nt][i] = 0.f;
    #pragma unroll
    for (int ks = 0; ks < 8; ks++) {
        uint32_t ah[2][4], al[2][4];
        load_afrag<SAP>(Ah, Al, wr * 32 + g, ks * 16 + tid4 * 2, ah, al);
        #pragma unroll
        for (int nt = 0; nt < 4; nt++) {
            uint4 b = __ldg(B1 + ((size_t)ks * 16 + (wc * 4 + nt)) * 32 + lane);
            #pragma unroll
            for (int mt = 0; mt < 2; mt++) mma16816(acc1[mt][nt], ah[mt], b.x, b.y);
            #pragma unroll
            for (int mt = 0; mt < 2; mt++) mma16816(acc1[mt][nt], ah[mt], b.z, b.w);
            #pragma unroll
            for (int mt = 0; mt < 2; mt++) mma16816(acc1[mt][nt], al[mt], b.x, b.y);
        }
    }
    #pragma unroll
    for (int mt = 0; mt < 2; mt++)
        #pragma unroll
        for (int half = 0; half < 2; half++) {
            int rl = wr * 32 + mt * 16 + g + half * 8;
            #pragma unroll
            for (int nt = 0; nt < 4; nt++) {
                int col = wc * 32 + nt * 8 + tid4 * 2;
                float o0 = acc1[mt][nt][half * 2 + 0];
                float o1 = acc1[mt][nt][half * 2 + 1];
                __nv_bfloat162 h = __floats2bfloat162_rn(o0, o1);
                __nv_bfloat162 l = __floats2bfloat162_rn(o0 - __bfloat162float(h.x),
                                                         o1 - __bfloat162float(h.y));
                *(__nv_bfloat162*)(Sh + rl * SAP + col) = h;
                *(__nv_bfloat162*)(Sl + rl * SAP + col) = l;
            }
        }
    __syncthreads();

    #pragma unroll 1
    for (int i = 0; i < 8; i++) {
        int rl = w * 8 + i;
        int er = row0 + rl;
        if (er >= M) break;
        int s = __ldg(src + er), d = __ldg(dst + er);
        __nv_bfloat162 h0 = *(__nv_bfloat162*)(Sh + rl * SAP + lane * 4);
        __nv_bfloat162 h1 = *(__nv_bfloat162*)(Sh + rl * SAP + lane * 4 + 2);
        __nv_bfloat162 l0 = *(__nv_bfloat162*)(Sl + rl * SAP + lane * 4);
        __nv_bfloat162 l1 = *(__nv_bfloat162*)(Sl + rl * SAP + lane * 4 + 2);
        float4 p;
        p.x = __bfloat162float(h0.x) + __bfloat162float(l0.x);
        p.y = __bfloat162float(h0.y) + __bfloat162float(l0.y);
        p.z = __bfloat162float(h1.x) + __bfloat162float(l1.x);
        p.w = __bfloat162float(h1.y) + __bfloat162float(l1.y);
        float4 q = __ldg((const float4*)(g_Q  + (size_t)d * D) + lane);
        float4 k = __ldg((const float4*)(g_Kb + (size_t)s * D) + lane);
        float4 sc;
        sc.x = k.x * q.x * 0.25f * p.x;
        sc.y = k.y * q.y * 0.25f * p.y;
        sc.z = k.z * q.z * 0.25f * p.z;
        sc.w = k.w * q.w * 0.25f * p.w;
        split_store(Sh, Sl, rl * SAP + lane * 4, sc);
        float part = sc.x + sc.y + sc.z + sc.w;
        part += __shfl_xor_sync(0xffffffffu, part, 1);
        part += __shfl_xor_sync(0xffffffffu, part, 2);
        part  = fminf(fmaxf(part, -5.f), 5.f);
        float sh = expf(part);
        float4 v = __ldg((const float4*)(g_V + (size_t)s * D) + lane);
        float* wv = g_wV + (size_t)d * D + lane * 4;
        asm volatile("red.global.add.v4.f32 [%0], {%1, %2, %3, %4};"
                     :: "l"(wv), "f"(v.x * sh), "f"(v.y * sh), "f"(v.z * sh), "f"(v.w * sh)
                     : "memory");
        if ((lane & 3) == 0) atomicAdd(g_z + (size_t)d * 8 + (lane >> 2), sh);
    }
    __syncthreads();

    float acc2[2][4][4];
    #pragma unroll
    for (int mt = 0; mt < 2; mt++)
        #pragma unroll
        for (int nt = 0; nt < 4; nt++)
            #pragma unroll
            for (int i = 0; i < 4; i++) acc2[mt][nt][i] = 0.f;
    #pragma unroll
    for (int ks = 0; ks < 8; ks++) {
        uint32_t ah[2][4], al[2][4];
        load_afrag<SAP>(Sh, Sl, wr * 32 + g, ks * 16 + tid4 * 2, ah, al);
        #pragma unroll
        for (int nt = 0; nt < 4; nt++) {
            uint4 b = __ldg(B2 + ((size_t)ks * 16 + (wc * 4 + nt)) * 32 + lane);
            #pragma unroll
            for (int mt = 0; mt < 2; mt++) mma16816(acc2[mt][nt], ah[mt], b.x, b.y);
            #pragma unroll
            for (int mt = 0; mt < 2; mt++) mma16816(acc2[mt][nt], ah[mt], b.z, b.w);
            #pragma unroll
            for (int mt = 0; mt < 2; mt++) mma16816(acc2[mt][nt], al[mt], b.x, b.y);
        }
    }

    float s1[8], s2[8];
    #pragma unroll
    for (int j = 0; j < 8; j++) { s1[j] = 0.f; s2[j] = 0.f; }
    #pragma unroll
    for (int mt = 0; mt < 2; mt++)
        #pragma unroll
        for (int half = 0; half < 2; half++) {
            int rl = wr * 32 + mt * 16 + g + half * 8;
            int gr = row0 + rl;
            if (gr >= M) continue;
            #pragma unroll
            for (int nt = 0; nt < 4; nt++) {
                int col = wc * 32 + nt * 8 + tid4 * 2;
                float o0 = acc2[mt][nt][half * 2 + 0] + __ldg(bias + col);
                float o1 = acc2[mt][nt][half * 2 + 1] + __ldg(bias + col + 1);
                __nv_bfloat162 rh  = *(__nv_bfloat162*)(Ah + rl * SAP + col);
                __nv_bfloat162 rlo = *(__nv_bfloat162*)(Al + rl * SAP + col);
                o0 += __bfloat162float(rh.x) + __bfloat162float(rlo.x);
                o1 += __bfloat162float(rh.y) + __bfloat162float(rlo.y);
                s1[nt * 2 + 0] += o0; s2[nt * 2 + 0] = fmaf(o0, o0, s2[nt * 2 + 0]);
                s1[nt * 2 + 1] += o1; s2[nt * 2 + 1] = fmaf(o1, o1, s2[nt * 2 + 1]);
                *(float2*)(C + (size_t)gr * 128 + col) = make_float2(o0, o1);
            }
        }
    #pragma unroll
    for (int j = 0; j < 8; j++) {
        float a = s1[j], q = s2[j];
        a += __shfl_xor_sync(0xffffffffu, a, 4);  q += __shfl_xor_sync(0xffffffffu, q, 4);
        a += __shfl_xor_sync(0xffffffffu, a, 8);  q += __shfl_xor_sync(0xffffffffu, q, 8);
        a += __shfl_xor_sync(0xffffffffu, a, 16); q += __shfl_xor_sync(0xffffffffu, q, 16);
        if (g == 0) {
            int col = wc * 32 + (j >> 1) * 8 + tid4 * 2 + (j & 1);
            atomicAdd(stats + col, a);
            atomicAdd(stats + 128 + col, q);
        }
    }
}

// ---------------- fused FFN, 64-row tiles ----------------
__global__ void __launch_bounds__(256)
ffn_k(const float* __restrict__ X, const __nv_bfloat16* __restrict__ W1img,
      const float* __restrict__ b1, const __nv_bfloat16* __restrict__ W2img,
      const float* __restrict__ b2, const float* __restrict__ bnab,
      float* __restrict__ stats, float* __restrict__ C, int M)
{
    constexpr int SAP = 136, MP = 264;
    extern __shared__ __nv_bfloat16 sm[];
    __nv_bfloat16* Ah = sm;
    __nv_bfloat16* Al = sm + 64 * SAP;
    __nv_bfloat16* Mh = sm;
    __nv_bfloat16* Ml = sm + 64 * MP;

    const int tid  = threadIdx.x;
    const int w    = tid >> 5, lane = tid & 31;
    const int wr   = w >> 2, wc = w & 3;
    const int g    = lane >> 2, tid4 = lane & 3;
    const int row0 = blockIdx.x * 64;

    const uint4* B1 = (const uint4*)W1img;
    const uint4* B2 = (const uint4*)W2img;

    #pragma unroll 2
    for (int i = tid; i < 2048; i += 256) {
        int r = i >> 5, c4 = i & 31, col = c4 * 4;
        float4 v = make_float4(0.f, 0.f, 0.f, 0.f);
        int gr = row0 + r;
        if (gr < M) {
            v = __ldg((const float4*)(X + (size_t)gr * 128) + c4);
            v.x = fmaf(v.x, __ldg(bnab + col + 0), __ldg(bnab + 128 + col + 0));
            v.y = fmaf(v.y, __ldg(bnab + col + 1), __ldg(bnab + 128 + col + 1));
            v.z = fmaf(v.z, __ldg(bnab + col + 2), __ldg(bnab + 128 + col + 2));
            v.w = fmaf(v.w, __ldg(bnab + col + 3), __ldg(bnab + 128 + col + 3));
        }
        split_store(Ah, Al, r * SAP + col, v);
    }
    __syncthreads();

    float acc1[2][8][4];
    #pragma unroll
    for (int mt = 0; mt < 2; mt++)
        #pragma unroll
        for (int nt = 0; nt < 8; nt++)
            #pragma unroll
            for (int i = 0; i < 4; i++) acc1[mt][nt][i] = 0.f;

    #pragma unroll
    for (int ks = 0; ks < 8; ks++) {
        uint32_t ah[2][4], al[2][4];
        load_afrag<SAP>(Ah, Al, wr * 32 + g, ks * 16 + tid4 * 2, ah, al);
        #pragma unroll
        for (int nt = 0; nt < 8; nt++) {
            uint4 b = __ldg(B1 + ((size_t)ks * 32 + (wc * 8 + nt)) * 32 + lane);
            #pragma unroll
            for (int mt = 0; mt < 2; mt++) mma16816(acc1[mt][nt], ah[mt], b.x, b.y);
            #pragma unroll
            for (int mt = 0; mt < 2; mt++) mma16816(acc1[mt][nt], ah[mt], b.z, b.w);
            #pragma unroll
            for (int mt = 0; mt < 2; mt++) mma16816(acc1[mt][nt], al[mt], b.x, b.y);
        }
    }
    __syncthreads();

    #pragma unroll
    for (int mt = 0; mt < 2; mt++)
        #pragma unroll
        for (int half = 0; half < 2; half++) {
            int rl = wr * 32 + mt * 16 + g + half * 8;
            #pragma unroll
            for (int nt = 0; nt < 8; nt++) {
                int col = wc * 64 + nt * 8 + tid4 * 2;
                float o0 = fmaxf(acc1[mt][nt][half * 2 + 0] + __ldg(b1 + col), 0.f);
                float o1 = fmaxf(acc1[mt][nt][half * 2 + 1] + __ldg(b1 + col + 1), 0.f);
                __nv_bfloat162 h = __floats2bfloat162_rn(o0, o1);
                __nv_bfloat162 l = __floats2bfloat162_rn(o0 - __bfloat162float(h.x),
                                                         o1 - __bfloat162float(h.y));
                *(__nv_bfloat162*)(Mh + rl * MP + col) = h;
                *(__nv_bfloat162*)(Ml + rl * MP + col) = l;
            }
        }
    __syncthreads();

    float acc2[2][4][4];
    #pragma unroll
    for (int mt = 0; mt < 2; mt++)
        #pragma unroll
        for (int nt = 0; nt < 4; nt++)
            #pragma unroll
            for (int i = 0; i < 4; i++) acc2[mt][nt][i] = 0.f;

    #pragma unroll
    for (int ks = 0; ks < 16; ks++) {
        uint32_t ah[2][4], al[2][4];
        load_afrag<MP>(Mh, Ml, wr * 32 + g, ks * 16 + tid4 * 2, ah, al);
        #pragma unroll
        for (int nt = 0; nt < 4; nt++) {
            uint4 b = __ldg(B2 + ((size_t)ks * 16 + (wc * 4 + nt)) * 32 + lane);
            #pragma unroll
            for (int mt = 0; mt < 2; mt++) mma16816(acc2[mt][nt], ah[mt], b.x, b.y);
            #pragma unroll
            for (int mt = 0; mt < 2; mt++) mma16816(acc2[mt][nt], ah[mt], b.z, b.w);
            #pragma unroll
            for (int mt = 0; mt < 2; mt++) mma16816(acc2[mt][nt], al[mt], b.x, b.y);
        }
    }

    float s1[8], s2[8];
    #pragma unroll
    for (int j = 0; j < 8; j++) { s1[j] = 0.f; s2[j] = 0.f; }
    #pragma unroll
    for (int mt = 0; mt < 2; mt++)
        #pragma unroll
        for (int half = 0; half < 2; half++) {
            int gr = row0 + wr * 32 + mt * 16 + g + half * 8;
            if (gr >= M) continue;
            #pragma unroll
            for (int nt = 0; nt < 4; nt++) {
                int col = wc * 32 + nt * 8 + tid4 * 2;
                float o0 = acc2[mt][nt][half * 2 + 0] + __ldg(b2 + col);
                float o1 = acc2[mt][nt][half * 2 + 1] + __ldg(b2 + col + 1);
                float2 rv = __ldg((const float2*)(X + (size_t)gr * 128 + col));
                o0 = fmaf(rv.x, __ldg(bnab + col),     o0 + __ldg(bnab + 128 + col));
                o1 = fmaf(rv.y, __ldg(bnab + col + 1), o1 + __ldg(bnab + 128 + col + 1));
                s1[nt * 2 + 0] += o0; s2[nt * 2 + 0] = fmaf(o0, o0, s2[nt * 2 + 0]);
                s1[nt * 2 + 1] += o1; s2[nt * 2 + 1] = fmaf(o1, o1, s2[nt * 2 + 1]);
                *(float2*)(C + (size_t)gr * 128 + col) = make_float2(o0, o1);
            }
        }
    #pragma unroll
    for (int j = 0; j < 8; j++) {
        float a = s1[j], q = s2[j];
        a += __shfl_xor_sync(0xffffffffu, a, 4);  q += __shfl_xor_sync(0xffffffffu, q, 4);
        a += __shfl_xor_sync(0xffffffffu, a, 8);  q += __shfl_xor_sync(0xffffffffu, q, 8);
        a += __shfl_xor_sync(0xffffffffu, a, 16); q += __shfl_xor_sync(0xffffffffu, q, 16);
        if (g == 0) {
            int col = wc * 32 + (j >> 1) * 8 + tid4 * 2 + (j & 1);
            atomicAdd(stats + col, a);
            atomicAdd(stats + 128 + col, q);
        }
    }
}

__global__ void finalize_bn(int bn, const float* __restrict__ g, const float* __restrict__ b, float minv)
{
    int c = threadIdx.x;
    float mean = g_stats[bn * 2 * D + c] * minv;
    float var  = g_stats[bn * 2 * D + D + c] * minv - mean * mean;
    float rstd = rsqrtf(var + 1e-5f);
    float scv  = g[c] * rstd;
    g_bnab[bn * 2 * D + c]     = scv;
    g_bnab[bn * 2 * D + D + c] = b[c] - mean * scv;
}

__global__ void out_norm(float* __restrict__ out)
{
    size_t i = (size_t)blockIdx.x * blockDim.x + threadIdx.x;
    if (i < (size_t)(NN + NE) * D) {
        int c  = (int)(i & 127);
        int bn = (i < (size_t)NN * D) ? 2 : 3;
        out[i] = fmaf(out[i], g_bnab[bn * 2 * D + c], g_bnab[bn * 2 * D + D + c]);
    }
}

// ---------------- host ----------------
extern "C" void kernel_launch(void* const* d_in, const int* in_sizes, int n_in,
                              void* d_out, int out_size)
{
    (void)in_sizes; (void)n_in; (void)out_size;
    const float* h_in  = (const float*)d_in[0];
    const float* e_in  = (const float*)d_in[1];
    const float* Wq    = (const float*)d_in[2];
    const float* Wk    = (const float*)d_in[3];
    const float* Wv    = (const float*)d_in[4];
    const float* We    = (const float*)d_in[5];
    const float* Ohw   = (const float*)d_in[6];
    const float* Ohb   = (const float*)d_in[7];
    const float* Oew   = (const float*)d_in[8];
    const float* Oeb   = (const float*)d_in[9];
    const float* bn1hg = (const float*)d_in[10];
    const float* bn1hb = (const float*)d_in[11];
    const float* bn1eg = (const float*)d_in[12];
    const float* bn1eb = (const float*)d_in[13];
    const float* fhw1  = (const float*)d_in[14];
    const float* fhb1  = (const float*)d_in[15];
    const float* fhw2  = (const float*)d_in[16];
    const float* fhb2  = (const float*)d_in[17];
    const float* few1  = (const float*)d_in[18];
    const float* feb1  = (const float*)d_in[19];
    const float* few2  = (const float*)d_in[20];
    const float* feb2  = (const float*)d_in[21];
    const float* bn2hg = (const float*)d_in[22];
    const float* bn2hb = (const float*)d_in[23];
    const float* bn2eg = (const float*)d_in[24];
    const float* bn2eb = (const float*)d_in[25];
    const int*   src   = (const int*)d_in[26];
    const int*   dst   = (const int*)d_in[27];

    float* out  = (float*)d_out;
    float* outh = out;
    float* oute = out + (size_t)NN * D;

    float *pQ, *pK, *pV, *pwV, *pz, *ph2, *pe2, *pstats, *pbnab;
    __nv_bfloat16* pimg;
    cudaGetSymbolAddress((void**)&pQ,    g_Q);
    cudaGetSymbolAddress((void**)&pK,    g_Kb);
    cudaGetSymbolAddress((void**)&pV,    g_V);
    cudaGetSymbolAddress((void**)&pwV,   g_wV);
    cudaGetSymbolAddress((void**)&pz,    g_z);
    cudaGetSymbolAddress((void**)&ph2,   g_h2);
    cudaGetSymbolAddress((void**)&pe2,   g_e2);
    cudaGetSymbolAddress((void**)&pstats, g_stats);
    cudaGetSymbolAddress((void**)&pbnab,  g_bnab);
    cudaGetSymbolAddress((void**)&pimg,   g_wimg);

    const size_t oWe = 0, oWq = 32768, oWk = 65536, oWv = 98304;
    const size_t oOh = 131072, oOe = 163840;
    const size_t oF1h = 196608, oF1e = 262144, oF2h = 327680, oF2e = 393216;

    auto kBh = mm_k<1, 1, 1, 1>;

    const int SMEM   = 2 * 128 * 136 * 2;
    const int SMEM_E = 4 * 64 * 136 * 2;
    const int SMEM_F = 2 * 64 * 264 * 2;
    cudaFuncSetAttribute(kBh,   cudaFuncAttributeMaxDynamicSharedMemorySize, SMEM);
    cudaFuncSetAttribute(qkv_k, cudaFuncAttributeMaxDynamicSharedMemorySize, SMEM);
    cudaFuncSetAttribute(epj_k, cudaFuncAttributeMaxDynamicSharedMemorySize, SMEM_E);
    cudaFuncSetAttribute(ffn_k, cudaFuncAttributeMaxDynamicSharedMemorySize, SMEM_F);

    const int gN   = (NN + 127) / 128;
    const int gN64 = (NN + 63) / 64;
    const int gE64 = (NE + 63) / 64;

    cudaMemsetAsync(pwV,    0, sizeof(float) * NN * D);
    cudaMemsetAsync(pz,     0, sizeof(float) * NN * 8);
    cudaMemsetAsync(pstats, 0, sizeof(float) * 4 * 2 * D);

    prep_w<<<64, 256>>>(We,  128, 128, pimg + oWe);
    prep_w<<<64, 256>>>(Wq,  128, 128, pimg + oWq);
    prep_w<<<64, 256>>>(Wk,  128, 128, pimg + oWk);
    prep_w<<<64, 256>>>(Wv,  128, 128, pimg + oWv);
    prep_w<<<64, 256>>>(Ohw, 128, 128, pimg + oOh);
    prep_w<<<64, 256>>>(Oew, 128, 128, pimg + oOe);
    prep_w<<<128, 256>>>(fhw1, 128, 256, pimg + oF1h);
    prep_w<<<128, 256>>>(few1, 128, 256, pimg + oF1e);
    prep_w<<<128, 256>>>(fhw2, 256, 128, pimg + oF2h);
    prep_w<<<128, 256>>>(few2, 256, 128, pimg + oF2e);

    qkv_k<<<dim3(1, gN), 256, SMEM>>>(h_in, pimg + oWq, pimg + oWk, pimg + oWv, pQ, pK, pV, NN);

    epj_k<<<gE64, 256, SMEM_E>>>(e_in, pimg + oWe, pimg + oOe, Oeb, src, dst,
                                 pstats + 1 * 2 * D, pe2, NE);

    kBh<<<dim3(1, gN), 256, SMEM>>>(pwV, pimg + oOh, Ohb, h_in, nullptr, pz,
                                    pstats + 0 * 2 * D, ph2, NN);
    finalize_bn<<<1, D>>>(0, bn1hg, bn1hb, 1.f / NN);
    finalize_bn<<<1, D>>>(1, bn1eg, bn1eb, 1.f / NE);

    ffn_k<<<gN64, 256, SMEM_F>>>(ph2, pimg + oF1h, fhb1, pimg + oF2h, fhb2, pbnab + 0 * 2 * D, pstats + 2 * 2 * D, outh, NN);
    ffn_k<<<gE64, 256, SMEM_F>>>(pe2, pimg + oF1e, feb1, pimg + oF2e, feb2, pbnab + 1 * 2 * D, pstats + 3 * 2 * D, oute, NE);

    finalize_bn<<<1, D>>>(2, bn2hg, bn2hb, 1.f / NN);
    finalize_bn<<<1, D>>>(3, bn2eg, bn2eb, 1.f / NE);

    out_norm<<<(int)(((size_t)(NN + NE) * D + 255) / 256), 256>>>(out);
}